// round 14
// baseline (speedup 1.0000x reference)
#include <cuda_runtime.h>
#include <cuda_bf16.h>
#include <math.h>
#include <stdint.h>

#define BATCH 2
#define TT    2048
#define TOK   (BATCH * TT)      // 4096
#define DD    1024
#define HH    16
#define HDIM  64
#define INNER (HH * HDIM)       // 1024
#define VOCAB 32000
#define FFN   (4 * DD)          // 4096

typedef __nv_bfloat16 bf16;

// ---------------- scratch ----------------
__device__ float g_h  [TOK * DD];
__device__ float g_qkv[TOK * 3 * INNER];

__device__ __align__(128) bf16 g_h1_hi[TOK * DD],     g_h1_lo[TOK * DD];
__device__ __align__(128) bf16 g_att_hi[TOK * INNER], g_att_lo[TOK * INNER];
__device__ __align__(128) bf16 g_ff1_hi[TOK * FFN],   g_ff1_lo[TOK * FFN];
__device__ __align__(128) bf16 g_hs_hi[TOK * DD],     g_hs_lo[TOK * DD];

__device__ __align__(128) bf16 g_wqkv_hi[DD * 3 * INNER], g_wqkv_lo[DD * 3 * INNER];
__device__ __align__(128) bf16 g_wout_hi[INNER * DD],     g_wout_lo[INNER * DD];
__device__ __align__(128) bf16 g_wf1_hi[DD * FFN],        g_wf1_lo[DD * FFN];
__device__ __align__(128) bf16 g_wf2_hi[FFN * DD],        g_wf2_lo[FFN * DD];
__device__ __align__(128) bf16 g_wh_hi[(size_t)DD * VOCAB], g_wh_lo[(size_t)DD * VOCAB];

// ---------------- helpers ----------------
__device__ __forceinline__ unsigned sptr(const void* p) {
    return (unsigned)__cvta_generic_to_shared(p);
}
__device__ __forceinline__ unsigned pack_bf16x2(bf16 a, bf16 b) {
    __nv_bfloat162 p = __halves2bfloat162(a, b);
    return *(unsigned*)&p;
}
__device__ __forceinline__ void split2(float v0, float v1, unsigned& hi, unsigned& lo) {
    bf16 h0 = __float2bfloat16(v0);
    bf16 h1 = __float2bfloat16(v1);
    bf16 l0 = __float2bfloat16(v0 - __bfloat162float(h0));
    bf16 l1 = __float2bfloat16(v1 - __bfloat162float(h1));
    hi = pack_bf16x2(h0, h1);
    lo = pack_bf16x2(l0, l1);
}
__device__ __forceinline__ float block_sum256(float v) {
    __shared__ float red[8];
    const unsigned FULL = 0xffffffffu;
    #pragma unroll
    for (int o = 16; o > 0; o >>= 1) v += __shfl_down_sync(FULL, v, o);
    __syncthreads();
    if ((threadIdx.x & 31) == 0) red[threadIdx.x >> 5] = v;
    __syncthreads();
    float s = 0.f;
    #pragma unroll
    for (int i = 0; i < 8; i++) s += red[i];
    return s;
}
__device__ __forceinline__ int fetch_token(const void* xraw, int t) {
    const int* x32 = (const int*)xraw;
    bool is64 = true;
    #pragma unroll
    for (int i = 0; i < 8; i++) if (x32[2 * i + 1] != 0) is64 = false;
    return is64 ? (int)(((const long long*)xraw)[t]) : x32[t];
}

// ---------------- fused weight split: all 5 weights, one launch ----------------
#define N4_QKV  (DD * 3 * INNER / 4)
#define N4_OUT  (INNER * DD / 4)
#define N4_FF1  (DD * FFN / 4)
#define N4_FF2  (FFN * DD / 4)
#define N4_HEAD (DD * VOCAB / 4)

__global__ void split_all_kernel(
    const float4* __restrict__ s0, uint2* __restrict__ h0, uint2* __restrict__ l0,
    const float4* __restrict__ s1, uint2* __restrict__ h1, uint2* __restrict__ l1,
    const float4* __restrict__ s2, uint2* __restrict__ h2, uint2* __restrict__ l2,
    const float4* __restrict__ s3, uint2* __restrict__ h3, uint2* __restrict__ l3,
    const float4* __restrict__ s4, uint2* __restrict__ h4, uint2* __restrict__ l4) {
    const long long total = (long long)N4_QKV + N4_OUT + N4_FF1 + N4_FF2 + N4_HEAD;
    for (long long i = (long long)blockIdx.x * blockDim.x + threadIdx.x; i < total;
         i += (long long)gridDim.x * blockDim.x) {
        const float4* s; uint2 *hh, *ll;
        long long j = i;
        if (j < N4_QKV)              { s = s0; hh = h0; ll = l0; }
        else if ((j -= N4_QKV) < N4_OUT) { s = s1; hh = h1; ll = l1; }
        else if ((j -= N4_OUT) < N4_FF1) { s = s2; hh = h2; ll = l2; }
        else if ((j -= N4_FF1) < N4_FF2) { s = s3; hh = h3; ll = l3; }
        else { j -= N4_FF2;            s = s4; hh = h4; ll = l4; }
        float4 v = s[j];
        unsigned a, b, c, d;
        split2(v.x, v.y, a, b);
        split2(v.z, v.w, c, d);
        hh[j] = make_uint2(a, c);
        ll[j] = make_uint2(b, d);
    }
}

// ---------------- embed + pos + LN1 ----------------
__global__ void embed_ln_kernel(const void* __restrict__ x,
                                const float* __restrict__ emb,
                                const float* __restrict__ pos,
                                const float* __restrict__ g,
                                const float* __restrict__ b,
                                float* __restrict__ h,
                                bf16* __restrict__ o_hi, bf16* __restrict__ o_lo) {
    const int t    = blockIdx.x;
    const int tpos = t & (TT - 1);
    const int tok = fetch_token(x, t);
    const float* e = emb + (size_t)tok * DD;
    const float* p = pos + (size_t)tpos * DD;

    float local[4];
    float s = 0.f;
    #pragma unroll
    for (int i = 0; i < 4; i++) {
        int idx = threadIdx.x + i * 256;
        float v = e[idx] + p[idx];
        local[i] = v;
        h[(size_t)t * DD + idx] = v;
        s += v;
    }
    float S = block_sum256(s);
    float mu = S * (1.0f / DD);
    float s2 = 0.f;
    #pragma unroll
    for (int i = 0; i < 4; i++) { float d = local[i] - mu; s2 += d * d; }
    float V = block_sum256(s2);
    float rstd = rsqrtf(V * (1.0f / DD) + 1e-5f);
    #pragma unroll
    for (int i = 0; i < 4; i++) {
        int idx = threadIdx.x + i * 256;
        float v = (local[i] - mu) * rstd * g[idx] + b[idx];
        bf16 hv = __float2bfloat16(v);
        o_hi[(size_t)t * DD + idx] = hv;
        o_lo[(size_t)t * DD + idx] = __float2bfloat16(v - __bfloat162float(hv));
    }
}

// ---------------- LN2 ----------------
__global__ void ln_kernel(const float* __restrict__ h,
                          const float* __restrict__ g,
                          const float* __restrict__ b,
                          bf16* __restrict__ o_hi, bf16* __restrict__ o_lo) {
    const int t = blockIdx.x;
    float local[4];
    float s = 0.f;
    #pragma unroll
    for (int i = 0; i < 4; i++) {
        int idx = threadIdx.x + i * 256;
        float v = h[(size_t)t * DD + idx];
        local[i] = v;
        s += v;
    }
    float S = block_sum256(s);
    float mu = S * (1.0f / DD);
    float s2 = 0.f;
    #pragma unroll
    for (int i = 0; i < 4; i++) { float d = local[i] - mu; s2 += d * d; }
    float V = block_sum256(s2);
    float rstd = rsqrtf(V * (1.0f / DD) + 1e-5f);
    #pragma unroll
    for (int i = 0; i < 4; i++) {
        int idx = threadIdx.x + i * 256;
        float v = (local[i] - mu) * rstd * g[idx] + b[idx];
        bf16 hv = __float2bfloat16(v);
        o_hi[(size_t)t * DD + idx] = hv;
        o_lo[(size_t)t * DD + idx] = __float2bfloat16(v - __bfloat162float(hv));
    }
}

// ================= mma.sync GEMM v4 (unchanged from round 13 — protected) =================
#define LDA_S   40
#define LDB_S   136
#define A_OFF_LO 10240
#define B_OFF_HI 20480
#define B_OFF_LO 29184
#define STAGE_B  37888
#define GSMEM_BYTES (2 * STAGE_B)

__device__ __forceinline__ void ldmatrix_x4(unsigned* r, unsigned addr) {
    asm volatile("ldmatrix.sync.aligned.m8n8.x4.shared.b16 {%0,%1,%2,%3}, [%4];"
                 : "=r"(r[0]), "=r"(r[1]), "=r"(r[2]), "=r"(r[3]) : "r"(addr));
}
__device__ __forceinline__ void ldmatrix_x4_trans(unsigned* r, unsigned addr) {
    asm volatile("ldmatrix.sync.aligned.m8n8.x4.trans.shared.b16 {%0,%1,%2,%3}, [%4];"
                 : "=r"(r[0]), "=r"(r[1]), "=r"(r[2]), "=r"(r[3]) : "r"(addr));
}
__device__ __forceinline__ void mma_bf16(float* c, const unsigned* a, const unsigned* b) {
    asm volatile("mma.sync.aligned.m16n8k16.row.col.f32.bf16.bf16.f32 "
                 "{%0,%1,%2,%3}, {%4,%5,%6,%7}, {%8,%9}, {%0,%1,%2,%3};"
                 : "+f"(c[0]), "+f"(c[1]), "+f"(c[2]), "+f"(c[3])
                 : "r"(a[0]), "r"(a[1]), "r"(a[2]), "r"(a[3]), "r"(b[0]), "r"(b[1]));
}
__device__ __forceinline__ void cp16(unsigned dst, const void* g) {
    asm volatile("cp.async.cg.shared.global [%0], [%1], 16;" :: "r"(dst), "l"(g));
}
__device__ __forceinline__ void cp_commit() { asm volatile("cp.async.commit_group;" ::: "memory"); }

template<int DO_BIAS, int DO_ADDC, int DO_GELU, int DO_SPLIT, int DO_F32>
__global__ __launch_bounds__(256, 2)
void gemm_bf3(int M, int N, int K,
              const bf16* __restrict__ Ah, const bf16* __restrict__ Al,
              const bf16* __restrict__ Bh, const bf16* __restrict__ Bl,
              const float* __restrict__ Cadd, const float* __restrict__ bias,
              float* __restrict__ D, bf16* __restrict__ Dh, bf16* __restrict__ Dl) {
    extern __shared__ __align__(16) char smraw[];
    const unsigned sbase = sptr(smraw);

    const int tid  = threadIdx.x;
    const int lane = tid & 31;
    const int warp = tid >> 5;
    const int wm   = warp & 3;
    const int wn   = warp >> 2;
    const int bm = blockIdx.x;   // M tile (fast dim)
    const int bn = blockIdx.y;   // N tile

    float acc[2][8][4];
    #pragma unroll
    for (int i = 0; i < 2; i++)
        #pragma unroll
        for (int j = 0; j < 8; j++)
            #pragma unroll
            for (int q = 0; q < 4; q++) acc[i][j][q] = 0.f;

    const int a_row = wm * 32 + (lane & 15);
    const int a_col = (lane >> 4) * 8;
    const int b_row = (lane & 15);
    const int b_col = wn * 64 + (lane >> 4) * 8;

    const int aL_r = tid >> 2;
    const int aL_k = (tid & 3) * 8;
    const int bL_r = tid >> 4;
    const int bL_k = (tid & 15) * 8;

    const size_t aG0 = (size_t)(bm * 128 + aL_r) * K + aL_k;
    const size_t bG0 = (size_t)bL_r * N + bn * 128 + bL_k;
    const unsigned sA0 = sbase + aL_r * (LDA_S * 2) + aL_k * 2;
    const unsigned sA1 = sbase + (aL_r + 64) * (LDA_S * 2) + aL_k * 2;
    const unsigned sB0 = sbase + B_OFF_HI + bL_r * (LDB_S * 2) + bL_k * 2;
    const unsigned sB1 = sbase + B_OFF_HI + (bL_r + 16) * (LDB_S * 2) + bL_k * 2;

    const int KT = K >> 5;

    auto load_stage = [&](int st, int kt) {
        const unsigned so = st * STAGE_B;
        const int k0 = kt << 5;
        cp16(sA0 + so,            Ah + aG0 + k0);
        cp16(sA1 + so,            Ah + aG0 + 64 * (size_t)K + k0);
        cp16(sA0 + so + A_OFF_LO, Al + aG0 + k0);
        cp16(sA1 + so + A_OFF_LO, Al + aG0 + 64 * (size_t)K + k0);
        const size_t bo0 = bG0 + (size_t)k0 * N;
        const size_t bo1 = bo0 + 16 * (size_t)N;
        cp16(sB0 + so,                         Bh + bo0);
        cp16(sB1 + so,                         Bh + bo1);
        cp16(sB0 + so + (B_OFF_LO - B_OFF_HI), Bl + bo0);
        cp16(sB1 + so + (B_OFF_LO - B_OFF_HI), Bl + bo1);
        cp_commit();
    };

    load_stage(0, 0);

    int st = 0;
    for (int kt = 0; kt < KT; kt++) {
        if (kt + 1 < KT) {
            load_stage(st ^ 1, kt + 1);
            asm volatile("cp.async.wait_group 1;" ::: "memory");
        } else {
            asm volatile("cp.async.wait_group 0;" ::: "memory");
        }
        __syncthreads();

        const unsigned so = sbase + st * STAGE_B;
        #pragma unroll
        for (int ks = 0; ks < 2; ks++) {
            unsigned ah[2][4], al[2][4];
            #pragma unroll
            for (int mt = 0; mt < 2; mt++) {
                unsigned arow_off = (a_row + mt * 16) * (LDA_S * 2) + (ks * 16 + a_col) * 2;
                ldmatrix_x4(ah[mt], so + arow_off);
                ldmatrix_x4(al[mt], so + A_OFF_LO + arow_off);
            }
            #pragma unroll
            for (int nh = 0; nh < 2; nh++) {
                unsigned bh[8], bl[8];
                #pragma unroll
                for (int ntp = 0; ntp < 2; ntp++) {
                    unsigned boff = (ks * 16 + b_row) * (LDB_S * 2) + (b_col + nh * 32 + ntp * 16) * 2;
                    ldmatrix_x4_trans(&bh[ntp * 4], so + B_OFF_HI + boff);
                    ldmatrix_x4_trans(&bl[ntp * 4], so + B_OFF_LO + boff);
                }
                #pragma unroll
                for (int mt = 0; mt < 2; mt++)
                    #pragma unroll
                    for (int nt = 0; nt < 4; nt++) {
                        float* a4 = acc[mt][nh * 4 + nt];
                        mma_bf16(a4, ah[mt], &bh[nt * 2]);
                        mma_bf16(a4, al[mt], &bh[nt * 2]);
                        mma_bf16(a4, ah[mt], &bl[nt * 2]);
                    }
            }
        }
        __syncthreads();
        st ^= 1;
    }

    // ---- epilogue ----
    const int row_base = bm * 128 + wm * 32 + (lane >> 2);
    const int col_base = bn * 128 + wn * 64 + (lane & 3) * 2;
    #pragma unroll
    for (int mt = 0; mt < 2; mt++) {
        #pragma unroll
        for (int nt = 0; nt < 8; nt++) {
            int col = col_base + nt * 8;
            float2 vb;
            if (DO_BIAS) vb = *(const float2*)&bias[col];
            #pragma unroll
            for (int half = 0; half < 2; half++) {
                int row = row_base + mt * 16 + half * 8;
                float v0 = acc[mt][nt][half * 2 + 0];
                float v1 = acc[mt][nt][half * 2 + 1];
                if (DO_BIAS) { v0 += vb.x; v1 += vb.y; }
                if (DO_GELU) { v0 = v0 * normcdff(v0); v1 = v1 * normcdff(v1); }
                size_t off = (size_t)row * N + col;
                if (DO_ADDC) {
                    float2 c = *(const float2*)&Cadd[off];
                    v0 += c.x; v1 += c.y;
                }
                if (DO_F32) {
                    float2 o; o.x = v0; o.y = v1;
                    *(float2*)&D[off] = o;
                }
                if (DO_SPLIT) {
                    unsigned hp, lp;
                    split2(v0, v1, hp, lp);
                    *(unsigned*)&Dh[off] = hp;
                    *(unsigned*)&Dl[off] = lp;
                }
            }
        }
    }
}

// ---------------- flash attention v2: 2 lanes per q-row, heavy blocks first ----------------
// 128 threads: row = qt*64 + (tid>>1), dim half = (tid&1)*32.
// Partner lanes (tid, tid^1) share a row: score = partial + shfl_xor(.,1).
// Softmax state duplicated deterministically in both partners.
__global__ __launch_bounds__(128)
void flash_attn_kernel(const float* __restrict__ qkv,
                       bf16* __restrict__ o_hi, bf16* __restrict__ o_lo) {
    const int tid = threadIdx.x;
    const int qt = gridDim.x - 1 - blockIdx.x;   // heavy tiles launch first
    const int hh = blockIdx.y;
    const int b  = blockIdx.z;

    __shared__ float k_sm[64 * 64];
    __shared__ float v_sm[64 * 64];

    const int rloc  = tid >> 1;        // 0..63
    const int dbase = (tid & 1) * 32;  // 0 or 32
    const int q_row = qt * 64 + rloc;
    const float* qp = qkv + ((size_t)(b * TT + q_row)) * (3 * INNER) + hh * HDIM + dbase;

    float q[32], acc[32];
    #pragma unroll
    for (int d = 0; d < 32; d++) { q[d] = qp[d] * 0.125f; acc[d] = 0.f; }
    float m = -3.0e38f, l = 0.f;

    for (int kt = 0; kt <= qt; kt++) {
        const float* kb = qkv + ((size_t)(b * TT + kt * 64)) * (3 * INNER) + INNER + hh * HDIM;
        const float* vb = kb + INNER;
        __syncthreads();
        #pragma unroll 8
        for (int i = 0; i < 32; i++) {
            int e = tid + i * 128;
            int r = e >> 6, cc = e & 63;
            k_sm[e] = kb[(size_t)r * (3 * INNER) + cc];
            v_sm[e] = vb[(size_t)r * (3 * INNER) + cc];
        }
        __syncthreads();

        const int valid = q_row - kt * 64;   // jj <= valid are unmasked
        #pragma unroll
        for (int c2 = 0; c2 < 2; c2++) {
            float s[32];
            float mt = -3.0e38f;
            for (int j = 0; j < 32; j++) {
                const int jj = c2 * 32 + j;
                float sp;
                if (jj <= valid) {
                    sp = 0.f;
                    #pragma unroll
                    for (int d = 0; d < 32; d++) sp += q[d] * k_sm[jj * 64 + dbase + d];
                } else {
                    sp = -1.5e38f;                 // sum of both halves = -3e38
                }
                sp += __shfl_xor_sync(0xffffffffu, sp, 1);
                s[j] = sp;
                mt = fmaxf(mt, sp);
            }
            if (mt > m) {
                float corr = expf(m - mt);
                l *= corr;
                #pragma unroll
                for (int d = 0; d < 32; d++) acc[d] *= corr;
                m = mt;
            }
            for (int j = 0; j < 32; j++) {
                float p = expf(s[j] - m);
                l += p;
                const int jj = c2 * 32 + j;
                #pragma unroll
                for (int d = 0; d < 32; d++) acc[d] += p * v_sm[jj * 64 + dbase + d];
            }
        }
    }

    const float inv = 1.0f / l;
    size_t base = ((size_t)(b * TT + q_row)) * INNER + hh * HDIM + dbase;
    #pragma unroll
    for (int d = 0; d < 32; d++) {
        float v = acc[d] * inv;
        bf16 hv = __float2bfloat16(v);
        o_hi[base + d] = hv;
        o_lo[base + d] = __float2bfloat16(v - __bfloat162float(hv));
    }
}

// ---------------- launch ----------------
extern "C" void kernel_launch(void* const* d_in, const int* in_sizes, int n_in,
                              void* d_out, int out_size) {
    const void*  x      = d_in[0];
    const float* emb    = (const float*)d_in[1];
    const float* pos    = (const float*)d_in[2];
    const float* w_qkv  = (const float*)d_in[3];
    const float* w_out  = (const float*)d_in[4];
    const float* ln1_g  = (const float*)d_in[5];
    const float* ln1_b  = (const float*)d_in[6];
    const float* ln2_g  = (const float*)d_in[7];
    const float* ln2_b  = (const float*)d_in[8];
    const float* w_ffn1 = (const float*)d_in[9];
    const float* b_ffn1 = (const float*)d_in[10];
    const float* w_ffn2 = (const float*)d_in[11];
    const float* b_ffn2 = (const float*)d_in[12];
    const float* w_head = (const float*)d_in[13];
    const float* b_head = (const float*)d_in[14];
    float* out = (float*)d_out;

    float *h, *qkv;
    bf16 *h1h, *h1l, *atth, *attl, *ff1h, *ff1l, *hsh, *hsl;
    bf16 *wqh, *wql, *woh, *wol, *w1h, *w1l, *w2h, *w2l, *whh, *whl;
    cudaGetSymbolAddress((void**)&h,    g_h);
    cudaGetSymbolAddress((void**)&qkv,  g_qkv);
    cudaGetSymbolAddress((void**)&h1h,  g_h1_hi);   cudaGetSymbolAddress((void**)&h1l,  g_h1_lo);
    cudaGetSymbolAddress((void**)&atth, g_att_hi);  cudaGetSymbolAddress((void**)&attl, g_att_lo);
    cudaGetSymbolAddress((void**)&ff1h, g_ff1_hi);  cudaGetSymbolAddress((void**)&ff1l, g_ff1_lo);
    cudaGetSymbolAddress((void**)&hsh,  g_hs_hi);   cudaGetSymbolAddress((void**)&hsl,  g_hs_lo);
    cudaGetSymbolAddress((void**)&wqh,  g_wqkv_hi); cudaGetSymbolAddress((void**)&wql,  g_wqkv_lo);
    cudaGetSymbolAddress((void**)&woh,  g_wout_hi); cudaGetSymbolAddress((void**)&wol,  g_wout_lo);
    cudaGetSymbolAddress((void**)&w1h,  g_wf1_hi);  cudaGetSymbolAddress((void**)&w1l,  g_wf1_lo);
    cudaGetSymbolAddress((void**)&w2h,  g_wf2_hi);  cudaGetSymbolAddress((void**)&w2l,  g_wf2_lo);
    cudaGetSymbolAddress((void**)&whh,  g_wh_hi);   cudaGetSymbolAddress((void**)&whl,  g_wh_lo);

    cudaFuncSetAttribute(gemm_bf3<0,0,0,0,1>, cudaFuncAttributeMaxDynamicSharedMemorySize, GSMEM_BYTES);
    cudaFuncSetAttribute(gemm_bf3<0,1,0,0,1>, cudaFuncAttributeMaxDynamicSharedMemorySize, GSMEM_BYTES);
    cudaFuncSetAttribute(gemm_bf3<1,0,1,1,0>, cudaFuncAttributeMaxDynamicSharedMemorySize, GSMEM_BYTES);
    cudaFuncSetAttribute(gemm_bf3<1,1,0,1,0>, cudaFuncAttributeMaxDynamicSharedMemorySize, GSMEM_BYTES);
    cudaFuncSetAttribute(gemm_bf3<1,0,0,0,1>, cudaFuncAttributeMaxDynamicSharedMemorySize, GSMEM_BYTES);

    // 0. fused weight split (one launch)
    split_all_kernel<<<2048, 256>>>(
        (const float4*)w_qkv,  (uint2*)wqh, (uint2*)wql,
        (const float4*)w_out,  (uint2*)woh, (uint2*)wol,
        (const float4*)w_ffn1, (uint2*)w1h, (uint2*)w1l,
        (const float4*)w_ffn2, (uint2*)w2h, (uint2*)w2l,
        (const float4*)w_head, (uint2*)whh, (uint2*)whl);

    // 1. embed + pos + ln1 -> h fp32, h1 split
    embed_ln_kernel<<<TOK, 256>>>(x, emb, pos, ln1_g, ln1_b, h, h1h, h1l);

    // 2. qkv = h1 @ w_qkv (fp32 out)       grid (M, N)
    gemm_bf3<0,0,0,0,1><<<dim3(TOK / 128, 3 * INNER / 128), 256, GSMEM_BYTES>>>(
        TOK, 3 * INNER, DD, h1h, h1l, wqh, wql, nullptr, nullptr, qkv, nullptr, nullptr);

    // 3. flash attention -> att split   (128 threads, heavy-first)
    flash_attn_kernel<<<dim3(TT / 64, HH, BATCH), 128>>>(qkv, atth, attl);

    // 4. h = h + att @ w_out (fp32, in place)
    gemm_bf3<0,1,0,0,1><<<dim3(TOK / 128, DD / 128), 256, GSMEM_BYTES>>>(
        TOK, DD, INNER, atth, attl, woh, wol, h, nullptr, h, nullptr, nullptr);

    // 5. h2 = ln2(h) -> split
    ln_kernel<<<TOK, 256>>>(h, ln2_g, ln2_b, h1h, h1l);

    // 6. ff1 = gelu(h2 @ w_ffn1 + b1) -> split
    gemm_bf3<1,0,1,1,0><<<dim3(TOK / 128, FFN / 128), 256, GSMEM_BYTES>>>(
        TOK, FFN, DD, h1h, h1l, w1h, w1l, nullptr, b_ffn1, nullptr, ff1h, ff1l);

    // 7. h' = h + ff1 @ w_ffn2 + b2 -> split (feeds head)
    gemm_bf3<1,1,0,1,0><<<dim3(TOK / 128, DD / 128), 256, GSMEM_BYTES>>>(
        TOK, DD, FFN, ff1h, ff1l, w2h, w2l, h, b_ffn2, nullptr, hsh, hsl);

    // 8. logits = h' @ w_head + b_head (fp32 out)
    gemm_bf3<1,0,0,0,1><<<dim3(TOK / 128, VOCAB / 128), 256, GSMEM_BYTES>>>(
        TOK, VOCAB, DD, hsh, hsl, whh, whl, nullptr, b_head, out, nullptr, nullptr);
}

// round 15
// speedup vs baseline: 1.1790x; 1.1790x over previous
#include <cuda_runtime.h>
#include <cuda_bf16.h>
#include <cuda_fp16.h>
#include <math.h>
#include <stdint.h>

#define BATCH 2
#define TT    2048
#define TOK   (BATCH * TT)      // 4096
#define DD    1024
#define HH    16
#define HDIM  64
#define INNER (HH * HDIM)       // 1024
#define VOCAB 32000
#define FFN   (4 * DD)          // 4096

typedef __nv_bfloat16 bf16;

// ---------------- scratch ----------------
__device__ float g_h  [TOK * DD];
__device__ float g_qkv[TOK * 3 * INNER];

__device__ __align__(128) bf16 g_h1_hi[TOK * DD],     g_h1_lo[TOK * DD];
__device__ __align__(128) bf16 g_att_hi[TOK * INNER], g_att_lo[TOK * INNER];
__device__ __align__(128) bf16 g_ff1_hi[TOK * FFN],   g_ff1_lo[TOK * FFN];
__device__ __align__(128) __half g_hs16_hi[TOK * DD], g_hs16_lo[TOK * DD];

__device__ __align__(128) bf16 g_wqkv_hi[DD * 3 * INNER], g_wqkv_lo[DD * 3 * INNER];
__device__ __align__(128) bf16 g_wout_hi[INNER * DD],     g_wout_lo[INNER * DD];
__device__ __align__(128) bf16 g_wf1_hi[DD * FFN],        g_wf1_lo[DD * FFN];
__device__ __align__(128) bf16 g_wf2_hi[FFN * DD],        g_wf2_lo[FFN * DD];
__device__ __align__(128) __half g_wh16[(size_t)DD * VOCAB];   // head weight, fp16 single

// ---------------- helpers ----------------
__device__ __forceinline__ unsigned sptr(const void* p) {
    return (unsigned)__cvta_generic_to_shared(p);
}
__device__ __forceinline__ unsigned pack_bf16x2(bf16 a, bf16 b) {
    __nv_bfloat162 p = __halves2bfloat162(a, b);
    return *(unsigned*)&p;
}
__device__ __forceinline__ void split2(float v0, float v1, unsigned& hi, unsigned& lo) {
    bf16 h0 = __float2bfloat16(v0);
    bf16 h1 = __float2bfloat16(v1);
    bf16 l0 = __float2bfloat16(v0 - __bfloat162float(h0));
    bf16 l1 = __float2bfloat16(v1 - __bfloat162float(h1));
    hi = pack_bf16x2(h0, h1);
    lo = pack_bf16x2(l0, l1);
}
__device__ __forceinline__ void split2h(float v0, float v1, unsigned& hi, unsigned& lo) {
    __half h0 = __float2half_rn(v0);
    __half h1 = __float2half_rn(v1);
    __half l0 = __float2half_rn(v0 - __half2float(h0));
    __half l1 = __float2half_rn(v1 - __half2float(h1));
    __half2 ph = __halves2half2(h0, h1);
    __half2 pl = __halves2half2(l0, l1);
    hi = *(unsigned*)&ph;
    lo = *(unsigned*)&pl;
}
__device__ __forceinline__ float block_sum256(float v) {
    __shared__ float red[8];
    const unsigned FULL = 0xffffffffu;
    #pragma unroll
    for (int o = 16; o > 0; o >>= 1) v += __shfl_down_sync(FULL, v, o);
    __syncthreads();
    if ((threadIdx.x & 31) == 0) red[threadIdx.x >> 5] = v;
    __syncthreads();
    float s = 0.f;
    #pragma unroll
    for (int i = 0; i < 8; i++) s += red[i];
    return s;
}
__device__ __forceinline__ int fetch_token(const void* xraw, int t) {
    const int* x32 = (const int*)xraw;
    bool is64 = true;
    #pragma unroll
    for (int i = 0; i < 8; i++) if (x32[2 * i + 1] != 0) is64 = false;
    return is64 ? (int)(((const long long*)xraw)[t]) : x32[t];
}

// ---------------- fused weight split: 4 layer weights (bf16 hi/lo) ----------------
#define N4_QKV  (DD * 3 * INNER / 4)
#define N4_OUT  (INNER * DD / 4)
#define N4_FF1  (DD * FFN / 4)
#define N4_FF2  (FFN * DD / 4)

__global__ void split_all_kernel(
    const float4* __restrict__ s0, uint2* __restrict__ h0, uint2* __restrict__ l0,
    const float4* __restrict__ s1, uint2* __restrict__ h1, uint2* __restrict__ l1,
    const float4* __restrict__ s2, uint2* __restrict__ h2, uint2* __restrict__ l2,
    const float4* __restrict__ s3, uint2* __restrict__ h3, uint2* __restrict__ l3) {
    const long long total = (long long)N4_QKV + N4_OUT + N4_FF1 + N4_FF2;
    for (long long i = (long long)blockIdx.x * blockDim.x + threadIdx.x; i < total;
         i += (long long)gridDim.x * blockDim.x) {
        const float4* s; uint2 *hh, *ll;
        long long j = i;
        if (j < N4_QKV)              { s = s0; hh = h0; ll = l0; }
        else if ((j -= N4_QKV) < N4_OUT) { s = s1; hh = h1; ll = l1; }
        else if ((j -= N4_OUT) < N4_FF1) { s = s2; hh = h2; ll = l2; }
        else { j -= N4_FF1;            s = s3; hh = h3; ll = l3; }
        float4 v = s[j];
        unsigned a, b, c, d;
        split2(v.x, v.y, a, b);
        split2(v.z, v.w, c, d);
        hh[j] = make_uint2(a, c);
        ll[j] = make_uint2(b, d);
    }
}

// ---------------- head weight: fp32 -> fp16 (single, round-to-nearest) ----------------
__global__ void cvt16_kernel(const float4* __restrict__ s, uint2* __restrict__ d, int n4) {
    int i = blockIdx.x * blockDim.x + threadIdx.x;
    int stride = gridDim.x * blockDim.x;
    for (; i < n4; i += stride) {
        float4 v = s[i];
        __half2 p0 = __halves2half2(__float2half_rn(v.x), __float2half_rn(v.y));
        __half2 p1 = __halves2half2(__float2half_rn(v.z), __float2half_rn(v.w));
        d[i] = make_uint2(*(unsigned*)&p0, *(unsigned*)&p1);
    }
}

// ---------------- embed + pos + LN1 ----------------
__global__ void embed_ln_kernel(const void* __restrict__ x,
                                const float* __restrict__ emb,
                                const float* __restrict__ pos,
                                const float* __restrict__ g,
                                const float* __restrict__ b,
                                float* __restrict__ h,
                                bf16* __restrict__ o_hi, bf16* __restrict__ o_lo) {
    const int t    = blockIdx.x;
    const int tpos = t & (TT - 1);
    const int tok = fetch_token(x, t);
    const float* e = emb + (size_t)tok * DD;
    const float* p = pos + (size_t)tpos * DD;

    float local[4];
    float s = 0.f;
    #pragma unroll
    for (int i = 0; i < 4; i++) {
        int idx = threadIdx.x + i * 256;
        float v = e[idx] + p[idx];
        local[i] = v;
        h[(size_t)t * DD + idx] = v;
        s += v;
    }
    float S = block_sum256(s);
    float mu = S * (1.0f / DD);
    float s2 = 0.f;
    #pragma unroll
    for (int i = 0; i < 4; i++) { float d = local[i] - mu; s2 += d * d; }
    float V = block_sum256(s2);
    float rstd = rsqrtf(V * (1.0f / DD) + 1e-5f);
    #pragma unroll
    for (int i = 0; i < 4; i++) {
        int idx = threadIdx.x + i * 256;
        float v = (local[i] - mu) * rstd * g[idx] + b[idx];
        bf16 hv = __float2bfloat16(v);
        o_hi[(size_t)t * DD + idx] = hv;
        o_lo[(size_t)t * DD + idx] = __float2bfloat16(v - __bfloat162float(hv));
    }
}

// ---------------- LN2 ----------------
__global__ void ln_kernel(const float* __restrict__ h,
                          const float* __restrict__ g,
                          const float* __restrict__ b,
                          bf16* __restrict__ o_hi, bf16* __restrict__ o_lo) {
    const int t = blockIdx.x;
    float local[4];
    float s = 0.f;
    #pragma unroll
    for (int i = 0; i < 4; i++) {
        int idx = threadIdx.x + i * 256;
        float v = h[(size_t)t * DD + idx];
        local[i] = v;
        s += v;
    }
    float S = block_sum256(s);
    float mu = S * (1.0f / DD);
    float s2 = 0.f;
    #pragma unroll
    for (int i = 0; i < 4; i++) { float d = local[i] - mu; s2 += d * d; }
    float V = block_sum256(s2);
    float rstd = rsqrtf(V * (1.0f / DD) + 1e-5f);
    #pragma unroll
    for (int i = 0; i < 4; i++) {
        int idx = threadIdx.x + i * 256;
        float v = (local[i] - mu) * rstd * g[idx] + b[idx];
        bf16 hv = __float2bfloat16(v);
        o_hi[(size_t)t * DD + idx] = hv;
        o_lo[(size_t)t * DD + idx] = __float2bfloat16(v - __bfloat162float(hv));
    }
}

// ================= mma.sync GEMM: PREC=0 bf16x3, PREC=1 fp16x2 (A split, B single) ========
// D(MxN) = A(MxK)@B(KxN). CTA 128x128, BK=32, 256 thr, 8 warps (4M x 2N).
// DO_SPLIT: 0 none, 1 bf16 hi/lo, 2 fp16 hi/lo.
#define LDA_S   40
#define LDB_S   136
#define A_OFF_LO 10240
#define B_OFF_HI 20480
#define B_OFF_LO 29184
#define STAGE_B  37888
#define GSMEM_BYTES (2 * STAGE_B)

__device__ __forceinline__ void ldmatrix_x4(unsigned* r, unsigned addr) {
    asm volatile("ldmatrix.sync.aligned.m8n8.x4.shared.b16 {%0,%1,%2,%3}, [%4];"
                 : "=r"(r[0]), "=r"(r[1]), "=r"(r[2]), "=r"(r[3]) : "r"(addr));
}
__device__ __forceinline__ void ldmatrix_x4_trans(unsigned* r, unsigned addr) {
    asm volatile("ldmatrix.sync.aligned.m8n8.x4.trans.shared.b16 {%0,%1,%2,%3}, [%4];"
                 : "=r"(r[0]), "=r"(r[1]), "=r"(r[2]), "=r"(r[3]) : "r"(addr));
}
__device__ __forceinline__ void mma_bf16(float* c, const unsigned* a, const unsigned* b) {
    asm volatile("mma.sync.aligned.m16n8k16.row.col.f32.bf16.bf16.f32 "
                 "{%0,%1,%2,%3}, {%4,%5,%6,%7}, {%8,%9}, {%0,%1,%2,%3};"
                 : "+f"(c[0]), "+f"(c[1]), "+f"(c[2]), "+f"(c[3])
                 : "r"(a[0]), "r"(a[1]), "r"(a[2]), "r"(a[3]), "r"(b[0]), "r"(b[1]));
}
__device__ __forceinline__ void mma_f16(float* c, const unsigned* a, const unsigned* b) {
    asm volatile("mma.sync.aligned.m16n8k16.row.col.f32.f16.f16.f32 "
                 "{%0,%1,%2,%3}, {%4,%5,%6,%7}, {%8,%9}, {%0,%1,%2,%3};"
                 : "+f"(c[0]), "+f"(c[1]), "+f"(c[2]), "+f"(c[3])
                 : "r"(a[0]), "r"(a[1]), "r"(a[2]), "r"(a[3]), "r"(b[0]), "r"(b[1]));
}
__device__ __forceinline__ void cp16(unsigned dst, const void* g) {
    asm volatile("cp.async.cg.shared.global [%0], [%1], 16;" :: "r"(dst), "l"(g));
}
__device__ __forceinline__ void cp_commit() { asm volatile("cp.async.commit_group;" ::: "memory"); }

template<int DO_BIAS, int DO_ADDC, int DO_GELU, int DO_SPLIT, int DO_F32, int PREC>
__global__ __launch_bounds__(256, 2)
void gemm_bf3(int M, int N, int K,
              const uint16_t* __restrict__ Ah, const uint16_t* __restrict__ Al,
              const uint16_t* __restrict__ Bh, const uint16_t* __restrict__ Bl,
              const float* __restrict__ Cadd, const float* __restrict__ bias,
              float* __restrict__ D, uint16_t* __restrict__ Dh, uint16_t* __restrict__ Dl) {
    extern __shared__ __align__(16) char smraw[];
    const unsigned sbase = sptr(smraw);

    const int tid  = threadIdx.x;
    const int lane = tid & 31;
    const int warp = tid >> 5;
    const int wm   = warp & 3;
    const int wn   = warp >> 2;
    const int bm = blockIdx.x;   // M tile (fast dim)
    const int bn = blockIdx.y;   // N tile

    float acc[2][8][4];
    #pragma unroll
    for (int i = 0; i < 2; i++)
        #pragma unroll
        for (int j = 0; j < 8; j++)
            #pragma unroll
            for (int q = 0; q < 4; q++) acc[i][j][q] = 0.f;

    const int a_row = wm * 32 + (lane & 15);
    const int a_col = (lane >> 4) * 8;
    const int b_row = (lane & 15);
    const int b_col = wn * 64 + (lane >> 4) * 8;

    const int aL_r = tid >> 2;
    const int aL_k = (tid & 3) * 8;
    const int bL_r = tid >> 4;
    const int bL_k = (tid & 15) * 8;

    const size_t aG0 = (size_t)(bm * 128 + aL_r) * K + aL_k;
    const size_t bG0 = (size_t)bL_r * N + bn * 128 + bL_k;
    const unsigned sA0 = sbase + aL_r * (LDA_S * 2) + aL_k * 2;
    const unsigned sA1 = sbase + (aL_r + 64) * (LDA_S * 2) + aL_k * 2;
    const unsigned sB0 = sbase + B_OFF_HI + bL_r * (LDB_S * 2) + bL_k * 2;
    const unsigned sB1 = sbase + B_OFF_HI + (bL_r + 16) * (LDB_S * 2) + bL_k * 2;

    const int KT = K >> 5;

    auto load_stage = [&](int st, int kt) {
        const unsigned so = st * STAGE_B;
        const int k0 = kt << 5;
        cp16(sA0 + so,            Ah + aG0 + k0);
        cp16(sA1 + so,            Ah + aG0 + 64 * (size_t)K + k0);
        cp16(sA0 + so + A_OFF_LO, Al + aG0 + k0);
        cp16(sA1 + so + A_OFF_LO, Al + aG0 + 64 * (size_t)K + k0);
        const size_t bo0 = bG0 + (size_t)k0 * N;
        const size_t bo1 = bo0 + 16 * (size_t)N;
        cp16(sB0 + so, Bh + bo0);
        cp16(sB1 + so, Bh + bo1);
        if (PREC == 0) {
            cp16(sB0 + so + (B_OFF_LO - B_OFF_HI), Bl + bo0);
            cp16(sB1 + so + (B_OFF_LO - B_OFF_HI), Bl + bo1);
        }
        cp_commit();
    };

    load_stage(0, 0);

    int st = 0;
    for (int kt = 0; kt < KT; kt++) {
        if (kt + 1 < KT) {
            load_stage(st ^ 1, kt + 1);
            asm volatile("cp.async.wait_group 1;" ::: "memory");
        } else {
            asm volatile("cp.async.wait_group 0;" ::: "memory");
        }
        __syncthreads();

        const unsigned so = sbase + st * STAGE_B;
        #pragma unroll
        for (int ks = 0; ks < 2; ks++) {
            unsigned ah[2][4], al[2][4];
            #pragma unroll
            for (int mt = 0; mt < 2; mt++) {
                unsigned arow_off = (a_row + mt * 16) * (LDA_S * 2) + (ks * 16 + a_col) * 2;
                ldmatrix_x4(ah[mt], so + arow_off);
                ldmatrix_x4(al[mt], so + A_OFF_LO + arow_off);
            }
            #pragma unroll
            for (int nh = 0; nh < 2; nh++) {
                unsigned bh[8], bl[8];
                #pragma unroll
                for (int ntp = 0; ntp < 2; ntp++) {
                    unsigned boff = (ks * 16 + b_row) * (LDB_S * 2) + (b_col + nh * 32 + ntp * 16) * 2;
                    ldmatrix_x4_trans(&bh[ntp * 4], so + B_OFF_HI + boff);
                    if (PREC == 0)
                        ldmatrix_x4_trans(&bl[ntp * 4], so + B_OFF_LO + boff);
                }
                #pragma unroll
                for (int mt = 0; mt < 2; mt++)
                    #pragma unroll
                    for (int nt = 0; nt < 4; nt++) {
                        float* a4 = acc[mt][nh * 4 + nt];
                        if (PREC == 0) {
                            mma_bf16(a4, ah[mt], &bh[nt * 2]);
                            mma_bf16(a4, al[mt], &bh[nt * 2]);
                            mma_bf16(a4, ah[mt], &bl[nt * 2]);
                        } else {
                            mma_f16(a4, ah[mt], &bh[nt * 2]);
                            mma_f16(a4, al[mt], &bh[nt * 2]);
                        }
                    }
            }
        }
        __syncthreads();
        st ^= 1;
    }

    // ---- epilogue ----
    const int row_base = bm * 128 + wm * 32 + (lane >> 2);
    const int col_base = bn * 128 + wn * 64 + (lane & 3) * 2;
    #pragma unroll
    for (int mt = 0; mt < 2; mt++) {
        #pragma unroll
        for (int nt = 0; nt < 8; nt++) {
            int col = col_base + nt * 8;
            float2 vb;
            if (DO_BIAS) vb = *(const float2*)&bias[col];
            #pragma unroll
            for (int half = 0; half < 2; half++) {
                int row = row_base + mt * 16 + half * 8;
                float v0 = acc[mt][nt][half * 2 + 0];
                float v1 = acc[mt][nt][half * 2 + 1];
                if (DO_BIAS) { v0 += vb.x; v1 += vb.y; }
                if (DO_GELU) { v0 = v0 * normcdff(v0); v1 = v1 * normcdff(v1); }
                size_t off = (size_t)row * N + col;
                if (DO_ADDC) {
                    float2 c = *(const float2*)&Cadd[off];
                    v0 += c.x; v1 += c.y;
                }
                if (DO_F32) {
                    float2 o; o.x = v0; o.y = v1;
                    *(float2*)&D[off] = o;
                }
                if (DO_SPLIT == 1) {
                    unsigned hp, lp;
                    split2(v0, v1, hp, lp);
                    *(unsigned*)&Dh[off] = hp;
                    *(unsigned*)&Dl[off] = lp;
                } else if (DO_SPLIT == 2) {
                    unsigned hp, lp;
                    split2h(v0, v1, hp, lp);
                    *(unsigned*)&Dh[off] = hp;
                    *(unsigned*)&Dl[off] = lp;
                }
            }
        }
    }
}

// ---------------- flash attention (round-13 v1: 64 threads, broadcast LDS) ----------------
__global__ __launch_bounds__(64)
void flash_attn_kernel(const float* __restrict__ qkv,
                       bf16* __restrict__ o_hi, bf16* __restrict__ o_lo) {
    const int tid = threadIdx.x;
    const int qt = blockIdx.x;
    const int hh = blockIdx.y;
    const int b  = blockIdx.z;

    __shared__ float k_sm[64 * 64];
    __shared__ float v_sm[64 * 64];

    const int q_row = qt * 64 + tid;
    const float* qp = qkv + ((size_t)(b * TT + q_row)) * (3 * INNER) + hh * HDIM;

    float q[64], acc[64];
    #pragma unroll
    for (int d = 0; d < 64; d++) { q[d] = qp[d] * 0.125f; acc[d] = 0.f; }
    float m = -3.0e38f, l = 0.f;

    for (int kt = 0; kt <= qt; kt++) {
        const float* kb = qkv + ((size_t)(b * TT + kt * 64)) * (3 * INNER) + INNER + hh * HDIM;
        const float* vb = kb + INNER;
        __syncthreads();
        for (int r = 0; r < 64; r++) {
            k_sm[r * 64 + tid] = kb[(size_t)r * (3 * INNER) + tid];
            v_sm[r * 64 + tid] = vb[(size_t)r * (3 * INNER) + tid];
        }
        __syncthreads();

        const int valid = q_row - kt * 64;
        #pragma unroll
        for (int c = 0; c < 2; c++) {
            float s[32];
            float mt = -3.0e38f;
            for (int j = 0; j < 32; j++) {
                const int jj = c * 32 + j;
                float sv;
                if (jj <= valid) {
                    sv = 0.f;
                    #pragma unroll
                    for (int d = 0; d < 64; d++) sv += q[d] * k_sm[jj * 64 + d];
                } else {
                    sv = -3.0e38f;
                }
                s[j] = sv;
                mt = fmaxf(mt, sv);
            }
            if (mt > m) {
                float corr = expf(m - mt);
                l *= corr;
                #pragma unroll
                for (int d = 0; d < 64; d++) acc[d] *= corr;
                m = mt;
            }
            for (int j = 0; j < 32; j++) {
                float p = expf(s[j] - m);
                l += p;
                const int jj = c * 32 + j;
                #pragma unroll
                for (int d = 0; d < 64; d++) acc[d] += p * v_sm[jj * 64 + d];
            }
        }
    }

    const float inv = 1.0f / l;
    size_t base = ((size_t)(b * TT + q_row)) * INNER + hh * HDIM;
    #pragma unroll
    for (int d = 0; d < 64; d++) {
        float v = acc[d] * inv;
        bf16 hv = __float2bfloat16(v);
        o_hi[base + d] = hv;
        o_lo[base + d] = __float2bfloat16(v - __bfloat162float(hv));
    }
}

// ---------------- launch ----------------
extern "C" void kernel_launch(void* const* d_in, const int* in_sizes, int n_in,
                              void* d_out, int out_size) {
    const void*  x      = d_in[0];
    const float* emb    = (const float*)d_in[1];
    const float* pos    = (const float*)d_in[2];
    const float* w_qkv  = (const float*)d_in[3];
    const float* w_out  = (const float*)d_in[4];
    const float* ln1_g  = (const float*)d_in[5];
    const float* ln1_b  = (const float*)d_in[6];
    const float* ln2_g  = (const float*)d_in[7];
    const float* ln2_b  = (const float*)d_in[8];
    const float* w_ffn1 = (const float*)d_in[9];
    const float* b_ffn1 = (const float*)d_in[10];
    const float* w_ffn2 = (const float*)d_in[11];
    const float* b_ffn2 = (const float*)d_in[12];
    const float* w_head = (const float*)d_in[13];
    const float* b_head = (const float*)d_in[14];
    float* out = (float*)d_out;

    float *h, *qkv;
    bf16 *h1h, *h1l, *atth, *attl, *ff1h, *ff1l;
    __half *hs16h, *hs16l, *wh16;
    bf16 *wqh, *wql, *woh, *wol, *w1h, *w1l, *w2h, *w2l;
    cudaGetSymbolAddress((void**)&h,     g_h);
    cudaGetSymbolAddress((void**)&qkv,   g_qkv);
    cudaGetSymbolAddress((void**)&h1h,   g_h1_hi);   cudaGetSymbolAddress((void**)&h1l,   g_h1_lo);
    cudaGetSymbolAddress((void**)&atth,  g_att_hi);  cudaGetSymbolAddress((void**)&attl,  g_att_lo);
    cudaGetSymbolAddress((void**)&ff1h,  g_ff1_hi);  cudaGetSymbolAddress((void**)&ff1l,  g_ff1_lo);
    cudaGetSymbolAddress((void**)&hs16h, g_hs16_hi); cudaGetSymbolAddress((void**)&hs16l, g_hs16_lo);
    cudaGetSymbolAddress((void**)&wqh,   g_wqkv_hi); cudaGetSymbolAddress((void**)&wql,   g_wqkv_lo);
    cudaGetSymbolAddress((void**)&woh,   g_wout_hi); cudaGetSymbolAddress((void**)&wol,   g_wout_lo);
    cudaGetSymbolAddress((void**)&w1h,   g_wf1_hi);  cudaGetSymbolAddress((void**)&w1l,   g_wf1_lo);
    cudaGetSymbolAddress((void**)&w2h,   g_wf2_hi);  cudaGetSymbolAddress((void**)&w2l,   g_wf2_lo);
    cudaGetSymbolAddress((void**)&wh16,  g_wh16);

    cudaFuncSetAttribute(gemm_bf3<0,0,0,0,1,0>, cudaFuncAttributeMaxDynamicSharedMemorySize, GSMEM_BYTES);
    cudaFuncSetAttribute(gemm_bf3<0,1,0,0,1,0>, cudaFuncAttributeMaxDynamicSharedMemorySize, GSMEM_BYTES);
    cudaFuncSetAttribute(gemm_bf3<1,0,1,1,0,0>, cudaFuncAttributeMaxDynamicSharedMemorySize, GSMEM_BYTES);
    cudaFuncSetAttribute(gemm_bf3<1,1,0,2,0,0>, cudaFuncAttributeMaxDynamicSharedMemorySize, GSMEM_BYTES);
    cudaFuncSetAttribute(gemm_bf3<1,0,0,0,1,1>, cudaFuncAttributeMaxDynamicSharedMemorySize, GSMEM_BYTES);

    // 0a. split 4 layer weights -> bf16 hi/lo
    split_all_kernel<<<2048, 256>>>(
        (const float4*)w_qkv,  (uint2*)wqh, (uint2*)wql,
        (const float4*)w_out,  (uint2*)woh, (uint2*)wol,
        (const float4*)w_ffn1, (uint2*)w1h, (uint2*)w1l,
        (const float4*)w_ffn2, (uint2*)w2h, (uint2*)w2l);
    // 0b. head weight -> fp16 single
    cvt16_kernel<<<2048, 256>>>((const float4*)w_head, (uint2*)wh16, DD * VOCAB / 4);

    // 1. embed + pos + ln1 -> h fp32, h1 split
    embed_ln_kernel<<<TOK, 256>>>(x, emb, pos, ln1_g, ln1_b, h, h1h, h1l);

    // 2. qkv = h1 @ w_qkv (fp32 out)
    gemm_bf3<0,0,0,0,1,0><<<dim3(TOK / 128, 3 * INNER / 128), 256, GSMEM_BYTES>>>(
        TOK, 3 * INNER, DD,
        (const uint16_t*)h1h, (const uint16_t*)h1l, (const uint16_t*)wqh, (const uint16_t*)wql,
        nullptr, nullptr, qkv, nullptr, nullptr);

    // 3. flash attention -> att split
    flash_attn_kernel<<<dim3(TT / 64, HH, BATCH), 64>>>(qkv, atth, attl);

    // 4. h = h + att @ w_out (fp32, in place)
    gemm_bf3<0,1,0,0,1,0><<<dim3(TOK / 128, DD / 128), 256, GSMEM_BYTES>>>(
        TOK, DD, INNER,
        (const uint16_t*)atth, (const uint16_t*)attl, (const uint16_t*)woh, (const uint16_t*)wol,
        h, nullptr, h, nullptr, nullptr);

    // 5. h2 = ln2(h) -> split
    ln_kernel<<<TOK, 256>>>(h, ln2_g, ln2_b, h1h, h1l);

    // 6. ff1 = gelu(h2 @ w_ffn1 + b1) -> bf16 split
    gemm_bf3<1,0,1,1,0,0><<<dim3(TOK / 128, FFN / 128), 256, GSMEM_BYTES>>>(
        TOK, FFN, DD,
        (const uint16_t*)h1h, (const uint16_t*)h1l, (const uint16_t*)w1h, (const uint16_t*)w1l,
        nullptr, b_ffn1, nullptr, (uint16_t*)ff1h, (uint16_t*)ff1l);

    // 7. h' = h + ff1 @ w_ffn2 + b2 -> fp16 split (feeds head)
    gemm_bf3<1,1,0,2,0,0><<<dim3(TOK / 128, DD / 128), 256, GSMEM_BYTES>>>(
        TOK, DD, FFN,
        (const uint16_t*)ff1h, (const uint16_t*)ff1l, (const uint16_t*)w2h, (const uint16_t*)w2l,
        h, b_ffn2, nullptr, (uint16_t*)hs16h, (uint16_t*)hs16l);

    // 8. logits = h' @ w_head + b_head (fp16x2, 2 passes, fp32 out)
    gemm_bf3<1,0,0,0,1,1><<<dim3(TOK / 128, VOCAB / 128), 256, GSMEM_BYTES>>>(
        TOK, VOCAB, DD,
        (const uint16_t*)hs16h, (const uint16_t*)hs16l, (const uint16_t*)wh16, nullptr,
        nullptr, b_head, out, nullptr, nullptr);
}

// round 16
// speedup vs baseline: 1.2594x; 1.0682x over previous
#include <cuda_runtime.h>
#include <cuda_bf16.h>
#include <cuda_fp16.h>
#include <math.h>
#include <stdint.h>

#define BATCH 2
#define TT    2048
#define TOK   (BATCH * TT)      // 4096
#define DD    1024
#define HH    16
#define HDIM  64
#define INNER (HH * HDIM)       // 1024
#define VOCAB 32000
#define FFN   (4 * DD)          // 4096

// ---------------- scratch ----------------
__device__ float g_h  [TOK * DD];
__device__ float g_qkv[TOK * 3 * INNER];

__device__ __align__(128) __half g_h1_hi[TOK * DD],     g_h1_lo[TOK * DD];
__device__ __align__(128) __half g_att_hi[TOK * INNER], g_att_lo[TOK * INNER];
__device__ __align__(128) __half g_ff1_hi[TOK * FFN],   g_ff1_lo[TOK * FFN];
__device__ __align__(128) __half g_hs_hi[TOK * DD],     g_hs_lo[TOK * DD];

// single-fp16 weights
__device__ __align__(128) __half g_wqkv16[DD * 3 * INNER];
__device__ __align__(128) __half g_wout16[INNER * DD];
__device__ __align__(128) __half g_wf116[DD * FFN];
__device__ __align__(128) __half g_wf216[FFN * DD];
__device__ __align__(128) __half g_wh16[(size_t)DD * VOCAB];

// ---------------- helpers ----------------
__device__ __forceinline__ unsigned sptr(const void* p) {
    return (unsigned)__cvta_generic_to_shared(p);
}
__device__ __forceinline__ void split2h(float v0, float v1, unsigned& hi, unsigned& lo) {
    __half h0 = __float2half_rn(v0);
    __half h1 = __float2half_rn(v1);
    __half l0 = __float2half_rn(v0 - __half2float(h0));
    __half l1 = __float2half_rn(v1 - __half2float(h1));
    __half2 ph = __halves2half2(h0, h1);
    __half2 pl = __halves2half2(l0, l1);
    hi = *(unsigned*)&ph;
    lo = *(unsigned*)&pl;
}
__device__ __forceinline__ float block_sum256(float v) {
    __shared__ float red[8];
    const unsigned FULL = 0xffffffffu;
    #pragma unroll
    for (int o = 16; o > 0; o >>= 1) v += __shfl_down_sync(FULL, v, o);
    __syncthreads();
    if ((threadIdx.x & 31) == 0) red[threadIdx.x >> 5] = v;
    __syncthreads();
    float s = 0.f;
    #pragma unroll
    for (int i = 0; i < 8; i++) s += red[i];
    return s;
}
__device__ __forceinline__ int fetch_token(const void* xraw, int t) {
    const int* x32 = (const int*)xraw;
    bool is64 = true;
    #pragma unroll
    for (int i = 0; i < 8; i++) if (x32[2 * i + 1] != 0) is64 = false;
    return is64 ? (int)(((const long long*)xraw)[t]) : x32[t];
}

// ---------------- fused weight convert: all 5 weights fp32 -> fp16 single ----------------
#define N4_QKV  (DD * 3 * INNER / 4)
#define N4_OUT  (INNER * DD / 4)
#define N4_FF1  (DD * FFN / 4)
#define N4_FF2  (FFN * DD / 4)
#define N4_HEAD (DD * VOCAB / 4)

__global__ void cvt_all_kernel(
    const float4* __restrict__ s0, uint2* __restrict__ d0,
    const float4* __restrict__ s1, uint2* __restrict__ d1,
    const float4* __restrict__ s2, uint2* __restrict__ d2,
    const float4* __restrict__ s3, uint2* __restrict__ d3,
    const float4* __restrict__ s4, uint2* __restrict__ d4) {
    const long long total = (long long)N4_QKV + N4_OUT + N4_FF1 + N4_FF2 + N4_HEAD;
    for (long long i = (long long)blockIdx.x * blockDim.x + threadIdx.x; i < total;
         i += (long long)gridDim.x * blockDim.x) {
        const float4* s; uint2* d;
        long long j = i;
        if (j < N4_QKV)                  { s = s0; d = d0; }
        else if ((j -= N4_QKV) < N4_OUT) { s = s1; d = d1; }
        else if ((j -= N4_OUT) < N4_FF1) { s = s2; d = d2; }
        else if ((j -= N4_FF1) < N4_FF2) { s = s3; d = d3; }
        else { j -= N4_FF2;                s = s4; d = d4; }
        float4 v = s[j];
        __half2 p0 = __halves2half2(__float2half_rn(v.x), __float2half_rn(v.y));
        __half2 p1 = __halves2half2(__float2half_rn(v.z), __float2half_rn(v.w));
        d[j] = make_uint2(*(unsigned*)&p0, *(unsigned*)&p1);
    }
}

// ---------------- embed + pos + LN1 (h fp32, h1 fp16 hi/lo) ----------------
__global__ void embed_ln_kernel(const void* __restrict__ x,
                                const float* __restrict__ emb,
                                const float* __restrict__ pos,
                                const float* __restrict__ g,
                                const float* __restrict__ b,
                                float* __restrict__ h,
                                __half* __restrict__ o_hi, __half* __restrict__ o_lo) {
    const int t    = blockIdx.x;
    const int tpos = t & (TT - 1);
    const int tok = fetch_token(x, t);
    const float* e = emb + (size_t)tok * DD;
    const float* p = pos + (size_t)tpos * DD;

    float local[4];
    float s = 0.f;
    #pragma unroll
    for (int i = 0; i < 4; i++) {
        int idx = threadIdx.x + i * 256;
        float v = e[idx] + p[idx];
        local[i] = v;
        h[(size_t)t * DD + idx] = v;
        s += v;
    }
    float S = block_sum256(s);
    float mu = S * (1.0f / DD);
    float s2 = 0.f;
    #pragma unroll
    for (int i = 0; i < 4; i++) { float d = local[i] - mu; s2 += d * d; }
    float V = block_sum256(s2);
    float rstd = rsqrtf(V * (1.0f / DD) + 1e-5f);
    #pragma unroll
    for (int i = 0; i < 4; i++) {
        int idx = threadIdx.x + i * 256;
        float v = (local[i] - mu) * rstd * g[idx] + b[idx];
        __half hv = __float2half_rn(v);
        o_hi[(size_t)t * DD + idx] = hv;
        o_lo[(size_t)t * DD + idx] = __float2half_rn(v - __half2float(hv));
    }
}

// ---------------- LN2 ----------------
__global__ void ln_kernel(const float* __restrict__ h,
                          const float* __restrict__ g,
                          const float* __restrict__ b,
                          __half* __restrict__ o_hi, __half* __restrict__ o_lo) {
    const int t = blockIdx.x;
    float local[4];
    float s = 0.f;
    #pragma unroll
    for (int i = 0; i < 4; i++) {
        int idx = threadIdx.x + i * 256;
        float v = h[(size_t)t * DD + idx];
        local[i] = v;
        s += v;
    }
    float S = block_sum256(s);
    float mu = S * (1.0f / DD);
    float s2 = 0.f;
    #pragma unroll
    for (int i = 0; i < 4; i++) { float d = local[i] - mu; s2 += d * d; }
    float V = block_sum256(s2);
    float rstd = rsqrtf(V * (1.0f / DD) + 1e-5f);
    #pragma unroll
    for (int i = 0; i < 4; i++) {
        int idx = threadIdx.x + i * 256;
        float v = (local[i] - mu) * rstd * g[idx] + b[idx];
        __half hv = __float2half_rn(v);
        o_hi[(size_t)t * DD + idx] = hv;
        o_lo[(size_t)t * DD + idx] = __float2half_rn(v - __half2float(hv));
    }
}

// ================= mma.sync GEMM fp16x2: A = Ah+Al (fp16 hi/lo), B single fp16 ==========
// D(MxN) = A(MxK)@B(KxN), 2 MMA passes: Ah*B + Al*B.
// CTA 128x128, BK=32, 256 thr, 8 warps (4M x 2N), warp tile 32x64.
// SMEM stage: A_hi[128*80B] A_lo[128*80B] B[32*272B] = 29184 B; 2 stages.
#define LDA_S   40
#define LDB_S   136
#define A_OFF_LO 10240
#define B_OFF    20480
#define STAGE_B  29184
#define GSMEM_BYTES (2 * STAGE_B)

__device__ __forceinline__ void ldmatrix_x4(unsigned* r, unsigned addr) {
    asm volatile("ldmatrix.sync.aligned.m8n8.x4.shared.b16 {%0,%1,%2,%3}, [%4];"
                 : "=r"(r[0]), "=r"(r[1]), "=r"(r[2]), "=r"(r[3]) : "r"(addr));
}
__device__ __forceinline__ void ldmatrix_x4_trans(unsigned* r, unsigned addr) {
    asm volatile("ldmatrix.sync.aligned.m8n8.x4.trans.shared.b16 {%0,%1,%2,%3}, [%4];"
                 : "=r"(r[0]), "=r"(r[1]), "=r"(r[2]), "=r"(r[3]) : "r"(addr));
}
__device__ __forceinline__ void mma_f16(float* c, const unsigned* a, const unsigned* b) {
    asm volatile("mma.sync.aligned.m16n8k16.row.col.f32.f16.f16.f32 "
                 "{%0,%1,%2,%3}, {%4,%5,%6,%7}, {%8,%9}, {%0,%1,%2,%3};"
                 : "+f"(c[0]), "+f"(c[1]), "+f"(c[2]), "+f"(c[3])
                 : "r"(a[0]), "r"(a[1]), "r"(a[2]), "r"(a[3]), "r"(b[0]), "r"(b[1]));
}
__device__ __forceinline__ void cp16(unsigned dst, const void* g) {
    asm volatile("cp.async.cg.shared.global [%0], [%1], 16;" :: "r"(dst), "l"(g));
}
__device__ __forceinline__ void cp_commit() { asm volatile("cp.async.commit_group;" ::: "memory"); }

template<int DO_BIAS, int DO_ADDC, int DO_GELU, int DO_SPLIT, int DO_F32>
__global__ __launch_bounds__(256, 2)
void gemm_h2(int M, int N, int K,
             const __half* __restrict__ Ah, const __half* __restrict__ Al,
             const __half* __restrict__ B,
             const float* __restrict__ Cadd, const float* __restrict__ bias,
             float* __restrict__ D, __half* __restrict__ Dh, __half* __restrict__ Dl) {
    extern __shared__ __align__(16) char smraw[];
    const unsigned sbase = sptr(smraw);

    const int tid  = threadIdx.x;
    const int lane = tid & 31;
    const int warp = tid >> 5;
    const int wm   = warp & 3;
    const int wn   = warp >> 2;
    const int bm = blockIdx.x;   // M tile (fast dim)
    const int bn = blockIdx.y;   // N tile

    float acc[2][8][4];
    #pragma unroll
    for (int i = 0; i < 2; i++)
        #pragma unroll
        for (int j = 0; j < 8; j++)
            #pragma unroll
            for (int q = 0; q < 4; q++) acc[i][j][q] = 0.f;

    const int a_row = wm * 32 + (lane & 15);
    const int a_col = (lane >> 4) * 8;
    const int b_row = (lane & 15);
    const int b_col = wn * 64 + (lane >> 4) * 8;

    const int aL_r = tid >> 2;            // A rows 0..63 (+64)
    const int aL_k = (tid & 3) * 8;
    const int bL_r = tid >> 4;            // B rows 0..15 (+16)
    const int bL_k = (tid & 15) * 8;

    const size_t aG0 = (size_t)(bm * 128 + aL_r) * K + aL_k;
    const size_t bG0 = (size_t)bL_r * N + bn * 128 + bL_k;
    const unsigned sA0 = sbase + aL_r * (LDA_S * 2) + aL_k * 2;
    const unsigned sA1 = sbase + (aL_r + 64) * (LDA_S * 2) + aL_k * 2;
    const unsigned sB0 = sbase + B_OFF + bL_r * (LDB_S * 2) + bL_k * 2;
    const unsigned sB1 = sbase + B_OFF + (bL_r + 16) * (LDB_S * 2) + bL_k * 2;

    const int KT = K >> 5;

    auto load_stage = [&](int st, int kt) {
        const unsigned so = st * STAGE_B;
        const int k0 = kt << 5;
        cp16(sA0 + so,            Ah + aG0 + k0);
        cp16(sA1 + so,            Ah + aG0 + 64 * (size_t)K + k0);
        cp16(sA0 + so + A_OFF_LO, Al + aG0 + k0);
        cp16(sA1 + so + A_OFF_LO, Al + aG0 + 64 * (size_t)K + k0);
        const size_t bo0 = bG0 + (size_t)k0 * N;
        cp16(sB0 + so, B + bo0);
        cp16(sB1 + so, B + bo0 + 16 * (size_t)N);
        cp_commit();
    };

    load_stage(0, 0);

    int st = 0;
    for (int kt = 0; kt < KT; kt++) {
        if (kt + 1 < KT) {
            load_stage(st ^ 1, kt + 1);
            asm volatile("cp.async.wait_group 1;" ::: "memory");
        } else {
            asm volatile("cp.async.wait_group 0;" ::: "memory");
        }
        __syncthreads();

        const unsigned so = sbase + st * STAGE_B;
        #pragma unroll
        for (int ks = 0; ks < 2; ks++) {
            unsigned ah[2][4], al[2][4];
            #pragma unroll
            for (int mt = 0; mt < 2; mt++) {
                unsigned arow_off = (a_row + mt * 16) * (LDA_S * 2) + (ks * 16 + a_col) * 2;
                ldmatrix_x4(ah[mt], so + arow_off);
                ldmatrix_x4(al[mt], so + A_OFF_LO + arow_off);
            }
            #pragma unroll
            for (int nh = 0; nh < 2; nh++) {
                unsigned bh[8];
                #pragma unroll
                for (int ntp = 0; ntp < 2; ntp++) {
                    unsigned boff = (ks * 16 + b_row) * (LDB_S * 2) + (b_col + nh * 32 + ntp * 16) * 2;
                    ldmatrix_x4_trans(&bh[ntp * 4], so + B_OFF + boff);
                }
                #pragma unroll
                for (int mt = 0; mt < 2; mt++)
                    #pragma unroll
                    for (int nt = 0; nt < 4; nt++) {
                        float* a4 = acc[mt][nh * 4 + nt];
                        mma_f16(a4, ah[mt], &bh[nt * 2]);
                        mma_f16(a4, al[mt], &bh[nt * 2]);
                    }
            }
        }
        __syncthreads();
        st ^= 1;
    }

    // ---- epilogue ----
    const int row_base = bm * 128 + wm * 32 + (lane >> 2);
    const int col_base = bn * 128 + wn * 64 + (lane & 3) * 2;
    #pragma unroll
    for (int mt = 0; mt < 2; mt++) {
        #pragma unroll
        for (int nt = 0; nt < 8; nt++) {
            int col = col_base + nt * 8;
            float2 vb;
            if (DO_BIAS) vb = *(const float2*)&bias[col];
            #pragma unroll
            for (int half = 0; half < 2; half++) {
                int row = row_base + mt * 16 + half * 8;
                float v0 = acc[mt][nt][half * 2 + 0];
                float v1 = acc[mt][nt][half * 2 + 1];
                if (DO_BIAS) { v0 += vb.x; v1 += vb.y; }
                if (DO_GELU) { v0 = v0 * normcdff(v0); v1 = v1 * normcdff(v1); }
                size_t off = (size_t)row * N + col;
                if (DO_ADDC) {
                    float2 c = *(const float2*)&Cadd[off];
                    v0 += c.x; v1 += c.y;
                }
                if (DO_F32) {
                    float2 o; o.x = v0; o.y = v1;
                    *(float2*)&D[off] = o;
                }
                if (DO_SPLIT) {
                    unsigned hp, lp;
                    split2h(v0, v1, hp, lp);
                    *(unsigned*)&Dh[off] = hp;
                    *(unsigned*)&Dl[off] = lp;
                }
            }
        }
    }
}

// ---------------- flash attention (round-13 v1, fp16 split out) ----------------
__global__ __launch_bounds__(64)
void flash_attn_kernel(const float* __restrict__ qkv,
                       __half* __restrict__ o_hi, __half* __restrict__ o_lo) {
    const int tid = threadIdx.x;
    const int qt = blockIdx.x;
    const int hh = blockIdx.y;
    const int b  = blockIdx.z;

    __shared__ float k_sm[64 * 64];
    __shared__ float v_sm[64 * 64];

    const int q_row = qt * 64 + tid;
    const float* qp = qkv + ((size_t)(b * TT + q_row)) * (3 * INNER) + hh * HDIM;

    float q[64], acc[64];
    #pragma unroll
    for (int d = 0; d < 64; d++) { q[d] = qp[d] * 0.125f; acc[d] = 0.f; }
    float m = -3.0e38f, l = 0.f;

    for (int kt = 0; kt <= qt; kt++) {
        const float* kb = qkv + ((size_t)(b * TT + kt * 64)) * (3 * INNER) + INNER + hh * HDIM;
        const float* vb = kb + INNER;
        __syncthreads();
        for (int r = 0; r < 64; r++) {
            k_sm[r * 64 + tid] = kb[(size_t)r * (3 * INNER) + tid];
            v_sm[r * 64 + tid] = vb[(size_t)r * (3 * INNER) + tid];
        }
        __syncthreads();

        const int valid = q_row - kt * 64;
        #pragma unroll
        for (int c = 0; c < 2; c++) {
            float s[32];
            float mt = -3.0e38f;
            for (int j = 0; j < 32; j++) {
                const int jj = c * 32 + j;
                float sv;
                if (jj <= valid) {
                    sv = 0.f;
                    #pragma unroll
                    for (int d = 0; d < 64; d++) sv += q[d] * k_sm[jj * 64 + d];
                } else {
                    sv = -3.0e38f;
                }
                s[j] = sv;
                mt = fmaxf(mt, sv);
            }
            if (mt > m) {
                float corr = expf(m - mt);
                l *= corr;
                #pragma unroll
                for (int d = 0; d < 64; d++) acc[d] *= corr;
                m = mt;
            }
            for (int j = 0; j < 32; j++) {
                float p = expf(s[j] - m);
                l += p;
                const int jj = c * 32 + j;
                #pragma unroll
                for (int d = 0; d < 64; d++) acc[d] += p * v_sm[jj * 64 + d];
            }
        }
    }

    const float inv = 1.0f / l;
    size_t base = ((size_t)(b * TT + q_row)) * INNER + hh * HDIM;
    #pragma unroll
    for (int d = 0; d < 64; d++) {
        float v = acc[d] * inv;
        __half hv = __float2half_rn(v);
        o_hi[base + d] = hv;
        o_lo[base + d] = __float2half_rn(v - __half2float(hv));
    }
}

// ---------------- launch ----------------
extern "C" void kernel_launch(void* const* d_in, const int* in_sizes, int n_in,
                              void* d_out, int out_size) {
    const void*  x      = d_in[0];
    const float* emb    = (const float*)d_in[1];
    const float* pos    = (const float*)d_in[2];
    const float* w_qkv  = (const float*)d_in[3];
    const float* w_out  = (const float*)d_in[4];
    const float* ln1_g  = (const float*)d_in[5];
    const float* ln1_b  = (const float*)d_in[6];
    const float* ln2_g  = (const float*)d_in[7];
    const float* ln2_b  = (const float*)d_in[8];
    const float* w_ffn1 = (const float*)d_in[9];
    const float* b_ffn1 = (const float*)d_in[10];
    const float* w_ffn2 = (const float*)d_in[11];
    const float* b_ffn2 = (const float*)d_in[12];
    const float* w_head = (const float*)d_in[13];
    const float* b_head = (const float*)d_in[14];
    float* out = (float*)d_out;

    float *h, *qkv;
    __half *h1h, *h1l, *atth, *attl, *ff1h, *ff1l, *hsh, *hsl;
    __half *wq16, *wo16, *w116, *w216, *wh16;
    cudaGetSymbolAddress((void**)&h,    g_h);
    cudaGetSymbolAddress((void**)&qkv,  g_qkv);
    cudaGetSymbolAddress((void**)&h1h,  g_h1_hi);   cudaGetSymbolAddress((void**)&h1l,  g_h1_lo);
    cudaGetSymbolAddress((void**)&atth, g_att_hi);  cudaGetSymbolAddress((void**)&attl, g_att_lo);
    cudaGetSymbolAddress((void**)&ff1h, g_ff1_hi);  cudaGetSymbolAddress((void**)&ff1l, g_ff1_lo);
    cudaGetSymbolAddress((void**)&hsh,  g_hs_hi);   cudaGetSymbolAddress((void**)&hsl,  g_hs_lo);
    cudaGetSymbolAddress((void**)&wq16, g_wqkv16);
    cudaGetSymbolAddress((void**)&wo16, g_wout16);
    cudaGetSymbolAddress((void**)&w116, g_wf116);
    cudaGetSymbolAddress((void**)&w216, g_wf216);
    cudaGetSymbolAddress((void**)&wh16, g_wh16);

    cudaFuncSetAttribute(gemm_h2<0,0,0,0,1>, cudaFuncAttributeMaxDynamicSharedMemorySize, GSMEM_BYTES);
    cudaFuncSetAttribute(gemm_h2<0,1,0,0,1>, cudaFuncAttributeMaxDynamicSharedMemorySize, GSMEM_BYTES);
    cudaFuncSetAttribute(gemm_h2<1,0,1,1,0>, cudaFuncAttributeMaxDynamicSharedMemorySize, GSMEM_BYTES);
    cudaFuncSetAttribute(gemm_h2<1,1,0,1,0>, cudaFuncAttributeMaxDynamicSharedMemorySize, GSMEM_BYTES);
    cudaFuncSetAttribute(gemm_h2<1,0,0,0,1>, cudaFuncAttributeMaxDynamicSharedMemorySize, GSMEM_BYTES);

    // 0. convert all weights -> fp16 single (one launch)
    cvt_all_kernel<<<2048, 256>>>(
        (const float4*)w_qkv,  (uint2*)wq16,
        (const float4*)w_out,  (uint2*)wo16,
        (const float4*)w_ffn1, (uint2*)w116,
        (const float4*)w_ffn2, (uint2*)w216,
        (const float4*)w_head, (uint2*)wh16);

    // 1. embed + pos + ln1 -> h fp32, h1 fp16 split
    embed_ln_kernel<<<TOK, 256>>>(x, emb, pos, ln1_g, ln1_b, h, h1h, h1l);

    // 2. qkv = h1 @ w_qkv (fp32 out)
    gemm_h2<0,0,0,0,1><<<dim3(TOK / 128, 3 * INNER / 128), 256, GSMEM_BYTES>>>(
        TOK, 3 * INNER, DD, h1h, h1l, wq16, nullptr, nullptr, qkv, nullptr, nullptr);

    // 3. flash attention -> att fp16 split
    flash_attn_kernel<<<dim3(TT / 64, HH, BATCH), 64>>>(qkv, atth, attl);

    // 4. h = h + att @ w_out (fp32, in place)
    gemm_h2<0,1,0,0,1><<<dim3(TOK / 128, DD / 128), 256, GSMEM_BYTES>>>(
        TOK, DD, INNER, atth, attl, wo16, h, nullptr, h, nullptr, nullptr);

    // 5. h2 = ln2(h) -> fp16 split
    ln_kernel<<<TOK, 256>>>(h, ln2_g, ln2_b, h1h, h1l);

    // 6. ff1 = gelu(h2 @ w_ffn1 + b1) -> fp16 split
    gemm_h2<1,0,1,1,0><<<dim3(TOK / 128, FFN / 128), 256, GSMEM_BYTES>>>(
        TOK, FFN, DD, h1h, h1l, w116, nullptr, b_ffn1, nullptr, ff1h, ff1l);

    // 7. h' = h + ff1 @ w_ffn2 + b2 -> fp16 split (feeds head)
    gemm_h2<1,1,0,1,0><<<dim3(TOK / 128, DD / 128), 256, GSMEM_BYTES>>>(
        TOK, DD, FFN, ff1h, ff1l, w216, h, b_ffn2, nullptr, hsh, hsl);

    // 8. logits = h' @ w_head + b_head (fp32 out)
    gemm_h2<1,0,0,0,1><<<dim3(TOK / 128, VOCAB / 128), 256, GSMEM_BYTES>>>(
        TOK, VOCAB, DD, hsh, hsl, wh16, nullptr, b_head, out, nullptr, nullptr);
}

// round 17
// speedup vs baseline: 1.2598x; 1.0003x over previous
#include <cuda_runtime.h>
#include <cuda_bf16.h>
#include <cuda_fp16.h>
#include <math.h>
#include <stdint.h>

#define BATCH 2
#define TT    2048
#define TOK   (BATCH * TT)      // 4096
#define DD    1024
#define HH    16
#define HDIM  64
#define INNER (HH * HDIM)       // 1024
#define VOCAB 32000
#define FFN   (4 * DD)          // 4096

// ---------------- scratch ----------------
__device__ float g_h  [TOK * DD];
__device__ float g_qkv[TOK * 3 * INNER];

__device__ __align__(128) __half g_h1_hi[TOK * DD],     g_h1_lo[TOK * DD];
__device__ __align__(128) __half g_att_hi[TOK * INNER], g_att_lo[TOK * INNER];
__device__ __align__(128) __half g_ff1_hi[TOK * FFN],   g_ff1_lo[TOK * FFN];
__device__ __align__(128) __half g_hs_hi[TOK * DD],     g_hs_lo[TOK * DD];

// single-fp16 weights
__device__ __align__(128) __half g_wqkv16[DD * 3 * INNER];
__device__ __align__(128) __half g_wout16[INNER * DD];
__device__ __align__(128) __half g_wf116[DD * FFN];
__device__ __align__(128) __half g_wf216[FFN * DD];
__device__ __align__(128) __half g_wh16[(size_t)DD * VOCAB];

// ---------------- helpers ----------------
__device__ __forceinline__ unsigned sptr(const void* p) {
    return (unsigned)__cvta_generic_to_shared(p);
}
__device__ __forceinline__ void split2h(float v0, float v1, unsigned& hi, unsigned& lo) {
    __half h0 = __float2half_rn(v0);
    __half h1 = __float2half_rn(v1);
    __half l0 = __float2half_rn(v0 - __half2float(h0));
    __half l1 = __float2half_rn(v1 - __half2float(h1));
    __half2 ph = __halves2half2(h0, h1);
    __half2 pl = __halves2half2(l0, l1);
    hi = *(unsigned*)&ph;
    lo = *(unsigned*)&pl;
}
__device__ __forceinline__ float block_sum256(float v) {
    __shared__ float red[8];
    const unsigned FULL = 0xffffffffu;
    #pragma unroll
    for (int o = 16; o > 0; o >>= 1) v += __shfl_down_sync(FULL, v, o);
    __syncthreads();
    if ((threadIdx.x & 31) == 0) red[threadIdx.x >> 5] = v;
    __syncthreads();
    float s = 0.f;
    #pragma unroll
    for (int i = 0; i < 8; i++) s += red[i];
    return s;
}
__device__ __forceinline__ int fetch_token(const void* xraw, int t) {
    const int* x32 = (const int*)xraw;
    bool is64 = true;
    #pragma unroll
    for (int i = 0; i < 8; i++) if (x32[2 * i + 1] != 0) is64 = false;
    return is64 ? (int)(((const long long*)xraw)[t]) : x32[t];
}

// ---------------- fused weight convert: all 5 weights fp32 -> fp16 single ----------------
#define N4_QKV  (DD * 3 * INNER / 4)
#define N4_OUT  (INNER * DD / 4)
#define N4_FF1  (DD * FFN / 4)
#define N4_FF2  (FFN * DD / 4)
#define N4_HEAD (DD * VOCAB / 4)

__global__ void cvt_all_kernel(
    const float4* __restrict__ s0, uint2* __restrict__ d0,
    const float4* __restrict__ s1, uint2* __restrict__ d1,
    const float4* __restrict__ s2, uint2* __restrict__ d2,
    const float4* __restrict__ s3, uint2* __restrict__ d3,
    const float4* __restrict__ s4, uint2* __restrict__ d4) {
    const long long total = (long long)N4_QKV + N4_OUT + N4_FF1 + N4_FF2 + N4_HEAD;
    for (long long i = (long long)blockIdx.x * blockDim.x + threadIdx.x; i < total;
         i += (long long)gridDim.x * blockDim.x) {
        const float4* s; uint2* d;
        long long j = i;
        if (j < N4_QKV)                  { s = s0; d = d0; }
        else if ((j -= N4_QKV) < N4_OUT) { s = s1; d = d1; }
        else if ((j -= N4_OUT) < N4_FF1) { s = s2; d = d2; }
        else if ((j -= N4_FF1) < N4_FF2) { s = s3; d = d3; }
        else { j -= N4_FF2;                s = s4; d = d4; }
        float4 v = s[j];
        __half2 p0 = __halves2half2(__float2half_rn(v.x), __float2half_rn(v.y));
        __half2 p1 = __halves2half2(__float2half_rn(v.z), __float2half_rn(v.w));
        d[j] = make_uint2(*(unsigned*)&p0, *(unsigned*)&p1);
    }
}

// ---------------- embed + pos + LN1 (h fp32, h1 fp16 hi/lo) ----------------
__global__ void embed_ln_kernel(const void* __restrict__ x,
                                const float* __restrict__ emb,
                                const float* __restrict__ pos,
                                const float* __restrict__ g,
                                const float* __restrict__ b,
                                float* __restrict__ h,
                                __half* __restrict__ o_hi, __half* __restrict__ o_lo) {
    const int t    = blockIdx.x;
    const int tpos = t & (TT - 1);
    const int tok = fetch_token(x, t);
    const float* e = emb + (size_t)tok * DD;
    const float* p = pos + (size_t)tpos * DD;

    float local[4];
    float s = 0.f;
    #pragma unroll
    for (int i = 0; i < 4; i++) {
        int idx = threadIdx.x + i * 256;
        float v = e[idx] + p[idx];
        local[i] = v;
        h[(size_t)t * DD + idx] = v;
        s += v;
    }
    float S = block_sum256(s);
    float mu = S * (1.0f / DD);
    float s2 = 0.f;
    #pragma unroll
    for (int i = 0; i < 4; i++) { float d = local[i] - mu; s2 += d * d; }
    float V = block_sum256(s2);
    float rstd = rsqrtf(V * (1.0f / DD) + 1e-5f);
    #pragma unroll
    for (int i = 0; i < 4; i++) {
        int idx = threadIdx.x + i * 256;
        float v = (local[i] - mu) * rstd * g[idx] + b[idx];
        __half hv = __float2half_rn(v);
        o_hi[(size_t)t * DD + idx] = hv;
        o_lo[(size_t)t * DD + idx] = __float2half_rn(v - __half2float(hv));
    }
}

// ---------------- LN2 ----------------
__global__ void ln_kernel(const float* __restrict__ h,
                          const float* __restrict__ g,
                          const float* __restrict__ b,
                          __half* __restrict__ o_hi, __half* __restrict__ o_lo) {
    const int t = blockIdx.x;
    float local[4];
    float s = 0.f;
    #pragma unroll
    for (int i = 0; i < 4; i++) {
        int idx = threadIdx.x + i * 256;
        float v = h[(size_t)t * DD + idx];
        local[i] = v;
        s += v;
    }
    float S = block_sum256(s);
    float mu = S * (1.0f / DD);
    float s2 = 0.f;
    #pragma unroll
    for (int i = 0; i < 4; i++) { float d = local[i] - mu; s2 += d * d; }
    float V = block_sum256(s2);
    float rstd = rsqrtf(V * (1.0f / DD) + 1e-5f);
    #pragma unroll
    for (int i = 0; i < 4; i++) {
        int idx = threadIdx.x + i * 256;
        float v = (local[i] - mu) * rstd * g[idx] + b[idx];
        __half hv = __float2half_rn(v);
        o_hi[(size_t)t * DD + idx] = hv;
        o_lo[(size_t)t * DD + idx] = __float2half_rn(v - __half2float(hv));
    }
}

// ================= mma.sync GEMM fp16x2: A = Ah+Al (fp16 hi/lo), B single fp16 ==========
// D(MxN) = A(MxK)@B(KxN), 2 MMA passes: Ah*B + Al*B.
// CTA 128x128, BK=32, 256 thr, 8 warps (4M x 2N), warp tile 32x64.
// SMEM stage: A_hi[128*80B] A_lo[128*80B] B[32*272B] = 29184 B; 2 stages.
#define LDA_S   40
#define LDB_S   136
#define A_OFF_LO 10240
#define B_OFF    20480
#define STAGE_B  29184
#define GSMEM_BYTES (2 * STAGE_B)

__device__ __forceinline__ void ldmatrix_x4(unsigned* r, unsigned addr) {
    asm volatile("ldmatrix.sync.aligned.m8n8.x4.shared.b16 {%0,%1,%2,%3}, [%4];"
                 : "=r"(r[0]), "=r"(r[1]), "=r"(r[2]), "=r"(r[3]) : "r"(addr));
}
__device__ __forceinline__ void ldmatrix_x4_trans(unsigned* r, unsigned addr) {
    asm volatile("ldmatrix.sync.aligned.m8n8.x4.trans.shared.b16 {%0,%1,%2,%3}, [%4];"
                 : "=r"(r[0]), "=r"(r[1]), "=r"(r[2]), "=r"(r[3]) : "r"(addr));
}
__device__ __forceinline__ void mma_f16(float* c, const unsigned* a, const unsigned* b) {
    asm volatile("mma.sync.aligned.m16n8k16.row.col.f32.f16.f16.f32 "
                 "{%0,%1,%2,%3}, {%4,%5,%6,%7}, {%8,%9}, {%0,%1,%2,%3};"
                 : "+f"(c[0]), "+f"(c[1]), "+f"(c[2]), "+f"(c[3])
                 : "r"(a[0]), "r"(a[1]), "r"(a[2]), "r"(a[3]), "r"(b[0]), "r"(b[1]));
}
__device__ __forceinline__ void cp16(unsigned dst, const void* g) {
    asm volatile("cp.async.cg.shared.global [%0], [%1], 16;" :: "r"(dst), "l"(g));
}
__device__ __forceinline__ void cp_commit() { asm volatile("cp.async.commit_group;" ::: "memory"); }

template<int DO_BIAS, int DO_ADDC, int DO_GELU, int DO_SPLIT, int DO_F32>
__global__ __launch_bounds__(256, 2)
void gemm_h2(int M, int N, int K,
             const __half* __restrict__ Ah, const __half* __restrict__ Al,
             const __half* __restrict__ B,
             const float* __restrict__ Cadd, const float* __restrict__ bias,
             float* __restrict__ D, __half* __restrict__ Dh, __half* __restrict__ Dl) {
    extern __shared__ __align__(16) char smraw[];
    const unsigned sbase = sptr(smraw);

    const int tid  = threadIdx.x;
    const int lane = tid & 31;
    const int warp = tid >> 5;
    const int wm   = warp & 3;
    const int wn   = warp >> 2;
    const int bm = blockIdx.x;   // M tile (fast dim)
    const int bn = blockIdx.y;   // N tile

    float acc[2][8][4];
    #pragma unroll
    for (int i = 0; i < 2; i++)
        #pragma unroll
        for (int j = 0; j < 8; j++)
            #pragma unroll
            for (int q = 0; q < 4; q++) acc[i][j][q] = 0.f;

    const int a_row = wm * 32 + (lane & 15);
    const int a_col = (lane >> 4) * 8;
    const int b_row = (lane & 15);
    const int b_col = wn * 64 + (lane >> 4) * 8;

    const int aL_r = tid >> 2;            // A rows 0..63 (+64)
    const int aL_k = (tid & 3) * 8;
    const int bL_r = tid >> 4;            // B rows 0..15 (+16)
    const int bL_k = (tid & 15) * 8;

    const size_t aG0 = (size_t)(bm * 128 + aL_r) * K + aL_k;
    const size_t bG0 = (size_t)bL_r * N + bn * 128 + bL_k;
    const unsigned sA0 = sbase + aL_r * (LDA_S * 2) + aL_k * 2;
    const unsigned sA1 = sbase + (aL_r + 64) * (LDA_S * 2) + aL_k * 2;
    const unsigned sB0 = sbase + B_OFF + bL_r * (LDB_S * 2) + bL_k * 2;
    const unsigned sB1 = sbase + B_OFF + (bL_r + 16) * (LDB_S * 2) + bL_k * 2;

    const int KT = K >> 5;

    auto load_stage = [&](int st, int kt) {
        const unsigned so = st * STAGE_B;
        const int k0 = kt << 5;
        cp16(sA0 + so,            Ah + aG0 + k0);
        cp16(sA1 + so,            Ah + aG0 + 64 * (size_t)K + k0);
        cp16(sA0 + so + A_OFF_LO, Al + aG0 + k0);
        cp16(sA1 + so + A_OFF_LO, Al + aG0 + 64 * (size_t)K + k0);
        const size_t bo0 = bG0 + (size_t)k0 * N;
        cp16(sB0 + so, B + bo0);
        cp16(sB1 + so, B + bo0 + 16 * (size_t)N);
        cp_commit();
    };

    load_stage(0, 0);

    int st = 0;
    for (int kt = 0; kt < KT; kt++) {
        if (kt + 1 < KT) {
            load_stage(st ^ 1, kt + 1);
            asm volatile("cp.async.wait_group 1;" ::: "memory");
        } else {
            asm volatile("cp.async.wait_group 0;" ::: "memory");
        }
        __syncthreads();

        const unsigned so = sbase + st * STAGE_B;
        #pragma unroll
        for (int ks = 0; ks < 2; ks++) {
            unsigned ah[2][4], al[2][4];
            #pragma unroll
            for (int mt = 0; mt < 2; mt++) {
                unsigned arow_off = (a_row + mt * 16) * (LDA_S * 2) + (ks * 16 + a_col) * 2;
                ldmatrix_x4(ah[mt], so + arow_off);
                ldmatrix_x4(al[mt], so + A_OFF_LO + arow_off);
            }
            #pragma unroll
            for (int nh = 0; nh < 2; nh++) {
                unsigned bh[8];
                #pragma unroll
                for (int ntp = 0; ntp < 2; ntp++) {
                    unsigned boff = (ks * 16 + b_row) * (LDB_S * 2) + (b_col + nh * 32 + ntp * 16) * 2;
                    ldmatrix_x4_trans(&bh[ntp * 4], so + B_OFF + boff);
                }
                #pragma unroll
                for (int mt = 0; mt < 2; mt++)
                    #pragma unroll
                    for (int nt = 0; nt < 4; nt++) {
                        float* a4 = acc[mt][nh * 4 + nt];
                        mma_f16(a4, ah[mt], &bh[nt * 2]);
                        mma_f16(a4, al[mt], &bh[nt * 2]);
                    }
            }
        }
        __syncthreads();
        st ^= 1;
    }

    // ---- epilogue ----
    const int row_base = bm * 128 + wm * 32 + (lane >> 2);
    const int col_base = bn * 128 + wn * 64 + (lane & 3) * 2;
    #pragma unroll
    for (int mt = 0; mt < 2; mt++) {
        #pragma unroll
        for (int nt = 0; nt < 8; nt++) {
            int col = col_base + nt * 8;
            float2 vb;
            if (DO_BIAS) vb = *(const float2*)&bias[col];
            #pragma unroll
            for (int half = 0; half < 2; half++) {
                int row = row_base + mt * 16 + half * 8;
                float v0 = acc[mt][nt][half * 2 + 0];
                float v1 = acc[mt][nt][half * 2 + 1];
                if (DO_BIAS) { v0 += vb.x; v1 += vb.y; }
                if (DO_GELU) { v0 = v0 * normcdff(v0); v1 = v1 * normcdff(v1); }
                size_t off = (size_t)row * N + col;
                if (DO_ADDC) {
                    float2 c = *(const float2*)&Cadd[off];
                    v0 += c.x; v1 += c.y;
                }
                if (DO_F32) {
                    float2 o; o.x = v0; o.y = v1;
                    *(float2*)&D[off] = o;
                }
                if (DO_SPLIT) {
                    unsigned hp, lp;
                    split2h(v0, v1, hp, lp);
                    *(unsigned*)&Dh[off] = hp;
                    *(unsigned*)&Dl[off] = lp;
                }
            }
        }
    }
}

// ---------------- flash attention (round-13 v1, fp16 split out) ----------------
__global__ __launch_bounds__(64)
void flash_attn_kernel(const float* __restrict__ qkv,
                       __half* __restrict__ o_hi, __half* __restrict__ o_lo) {
    const int tid = threadIdx.x;
    const int qt = blockIdx.x;
    const int hh = blockIdx.y;
    const int b  = blockIdx.z;

    __shared__ float k_sm[64 * 64];
    __shared__ float v_sm[64 * 64];

    const int q_row = qt * 64 + tid;
    const float* qp = qkv + ((size_t)(b * TT + q_row)) * (3 * INNER) + hh * HDIM;

    float q[64], acc[64];
    #pragma unroll
    for (int d = 0; d < 64; d++) { q[d] = qp[d] * 0.125f; acc[d] = 0.f; }
    float m = -3.0e38f, l = 0.f;

    for (int kt = 0; kt <= qt; kt++) {
        const float* kb = qkv + ((size_t)(b * TT + kt * 64)) * (3 * INNER) + INNER + hh * HDIM;
        const float* vb = kb + INNER;
        __syncthreads();
        for (int r = 0; r < 64; r++) {
            k_sm[r * 64 + tid] = kb[(size_t)r * (3 * INNER) + tid];
            v_sm[r * 64 + tid] = vb[(size_t)r * (3 * INNER) + tid];
        }
        __syncthreads();

        const int valid = q_row - kt * 64;
        #pragma unroll
        for (int c = 0; c < 2; c++) {
            float s[32];
            float mt = -3.0e38f;
            for (int j = 0; j < 32; j++) {
                const int jj = c * 32 + j;
                float sv;
                if (jj <= valid) {
                    sv = 0.f;
                    #pragma unroll
                    for (int d = 0; d < 64; d++) sv += q[d] * k_sm[jj * 64 + d];
                } else {
                    sv = -3.0e38f;
                }
                s[j] = sv;
                mt = fmaxf(mt, sv);
            }
            if (mt > m) {
                float corr = expf(m - mt);
                l *= corr;
                #pragma unroll
                for (int d = 0; d < 64; d++) acc[d] *= corr;
                m = mt;
            }
            for (int j = 0; j < 32; j++) {
                float p = expf(s[j] - m);
                l += p;
                const int jj = c * 32 + j;
                #pragma unroll
                for (int d = 0; d < 64; d++) acc[d] += p * v_sm[jj * 64 + d];
            }
        }
    }

    const float inv = 1.0f / l;
    size_t base = ((size_t)(b * TT + q_row)) * INNER + hh * HDIM;
    #pragma unroll
    for (int d = 0; d < 64; d++) {
        float v = acc[d] * inv;
        __half hv = __float2half_rn(v);
        o_hi[base + d] = hv;
        o_lo[base + d] = __float2half_rn(v - __half2float(hv));
    }
}

// ---------------- launch ----------------
extern "C" void kernel_launch(void* const* d_in, const int* in_sizes, int n_in,
                              void* d_out, int out_size) {
    const void*  x      = d_in[0];
    const float* emb    = (const float*)d_in[1];
    const float* pos    = (const float*)d_in[2];
    const float* w_qkv  = (const float*)d_in[3];
    const float* w_out  = (const float*)d_in[4];
    const float* ln1_g  = (const float*)d_in[5];
    const float* ln1_b  = (const float*)d_in[6];
    const float* ln2_g  = (const float*)d_in[7];
    const float* ln2_b  = (const float*)d_in[8];
    const float* w_ffn1 = (const float*)d_in[9];
    const float* b_ffn1 = (const float*)d_in[10];
    const float* w_ffn2 = (const float*)d_in[11];
    const float* b_ffn2 = (const float*)d_in[12];
    const float* w_head = (const float*)d_in[13];
    const float* b_head = (const float*)d_in[14];
    float* out = (float*)d_out;

    float *h, *qkv;
    __half *h1h, *h1l, *atth, *attl, *ff1h, *ff1l, *hsh, *hsl;
    __half *wq16, *wo16, *w116, *w216, *wh16;
    cudaGetSymbolAddress((void**)&h,    g_h);
    cudaGetSymbolAddress((void**)&qkv,  g_qkv);
    cudaGetSymbolAddress((void**)&h1h,  g_h1_hi);   cudaGetSymbolAddress((void**)&h1l,  g_h1_lo);
    cudaGetSymbolAddress((void**)&atth, g_att_hi);  cudaGetSymbolAddress((void**)&attl, g_att_lo);
    cudaGetSymbolAddress((void**)&ff1h, g_ff1_hi);  cudaGetSymbolAddress((void**)&ff1l, g_ff1_lo);
    cudaGetSymbolAddress((void**)&hsh,  g_hs_hi);   cudaGetSymbolAddress((void**)&hsl,  g_hs_lo);
    cudaGetSymbolAddress((void**)&wq16, g_wqkv16);
    cudaGetSymbolAddress((void**)&wo16, g_wout16);
    cudaGetSymbolAddress((void**)&w116, g_wf116);
    cudaGetSymbolAddress((void**)&w216, g_wf216);
    cudaGetSymbolAddress((void**)&wh16, g_wh16);

    cudaFuncSetAttribute(gemm_h2<0,0,0,0,1>, cudaFuncAttributeMaxDynamicSharedMemorySize, GSMEM_BYTES);
    cudaFuncSetAttribute(gemm_h2<0,1,0,0,1>, cudaFuncAttributeMaxDynamicSharedMemorySize, GSMEM_BYTES);
    cudaFuncSetAttribute(gemm_h2<1,0,1,1,0>, cudaFuncAttributeMaxDynamicSharedMemorySize, GSMEM_BYTES);
    cudaFuncSetAttribute(gemm_h2<1,1,0,1,0>, cudaFuncAttributeMaxDynamicSharedMemorySize, GSMEM_BYTES);
    cudaFuncSetAttribute(gemm_h2<1,0,0,0,1>, cudaFuncAttributeMaxDynamicSharedMemorySize, GSMEM_BYTES);

    // 0. convert all weights -> fp16 single (one launch)
    cvt_all_kernel<<<2048, 256>>>(
        (const float4*)w_qkv,  (uint2*)wq16,
        (const float4*)w_out,  (uint2*)wo16,
        (const float4*)w_ffn1, (uint2*)w116,
        (const float4*)w_ffn2, (uint2*)w216,
        (const float4*)w_head, (uint2*)wh16);

    // 1. embed + pos + ln1 -> h fp32, h1 fp16 split
    embed_ln_kernel<<<TOK, 256>>>(x, emb, pos, ln1_g, ln1_b, h, h1h, h1l);

    // 2. qkv = h1 @ w_qkv (fp32 out)
    gemm_h2<0,0,0,0,1><<<dim3(TOK / 128, 3 * INNER / 128), 256, GSMEM_BYTES>>>(
        TOK, 3 * INNER, DD, h1h, h1l, wq16, nullptr, nullptr, qkv, nullptr, nullptr);

    // 3. flash attention -> att fp16 split
    flash_attn_kernel<<<dim3(TT / 64, HH, BATCH), 64>>>(qkv, atth, attl);

    // 4. h = h + att @ w_out (fp32, in place)
    gemm_h2<0,1,0,0,1><<<dim3(TOK / 128, DD / 128), 256, GSMEM_BYTES>>>(
        TOK, DD, INNER, atth, attl, wo16, h, nullptr, h, nullptr, nullptr);

    // 5. h2 = ln2(h) -> fp16 split
    ln_kernel<<<TOK, 256>>>(h, ln2_g, ln2_b, h1h, h1l);

    // 6. ff1 = gelu(h2 @ w_ffn1 + b1) -> fp16 split
    gemm_h2<1,0,1,1,0><<<dim3(TOK / 128, FFN / 128), 256, GSMEM_BYTES>>>(
        TOK, FFN, DD, h1h, h1l, w116, nullptr, b_ffn1, nullptr, ff1h, ff1l);

    // 7. h' = h + ff1 @ w_ffn2 + b2 -> fp16 split (feeds head)
    gemm_h2<1,1,0,1,0><<<dim3(TOK / 128, DD / 128), 256, GSMEM_BYTES>>>(
        TOK, DD, FFN, ff1h, ff1l, w216, h, b_ffn2, nullptr, hsh, hsl);

    // 8. logits = h' @ w_head + b_head (fp32 out)
    gemm_h2<1,0,0,0,1><<<dim3(TOK / 128, VOCAB / 128), 256, GSMEM_BYTES>>>(
        TOK, VOCAB, DD, hsh, hsl, wh16, nullptr, b_head, out, nullptr, nullptr);
}